// round 9
// baseline (speedup 1.0000x reference)
#include <cuda_runtime.h>
#include <cuda_bf16.h>
#include <math.h>
#include <stdint.h>

#define N       16384
#define IN_DIM  5000
#define HID     64
#define NCLS    4
#define NLEV    11
#define KSPLIT  16
#define KCHUNK  (N / KSPLIT)               /* 1024 */
#define KT      64
#define STAGES_A (KCHUNK / KT)             /* 16 */
#define STAGES_E ((IN_DIM + KT - 1) / KT)  /* 79 */
#define RROWS   64
#define THREADS 128
#define AGG_BLKS 512
#define GRU_BLKS 64
#define EMB_BLKS (N / RROWS)               /* 256 */

// agg/fat dynamic smem layout (bytes)
#define OFF_AH   0                          /* 64 x 72 bf16 = 9216 */
#define OFF_AL   9216
#define OFF_B    18432                      /* 2 bufs x (Bh 9216 + Bl 9216) */
#define BUF_STRIDE 18432
#define OFF_ROWS 55296                      /* 64 ints */
#define OFF_FLAG 55552
#define SMEM_AGG 55600

#define A_ROW 144                           /* (KT+8)*2 bytes */
#define B_ROW 144                           /* (HID+8)*2 bytes */

// gru scratch layout (within reused smem)
#define GR_U   0                            /* 64 x 66 f32 = 16896 */
#define GR_HS  16896                        /* 32 x 66 f32 = 8448 */
#define GR_RH  25344                        /* 8448 -> ends 33792 */

// ---------------- device scratch ----------------
__device__ float g_h  [N * HID];
__device__ float g_hs [N * HID];
__device__ float g_xr [N * HID];
__device__ float g_xz [N * HID];
__device__ float g_xh [N * HID];
__device__ __nv_bfloat16 g_hbh[N * HID];
__device__ __nv_bfloat16 g_hbl[N * HID];
__device__ int   g_order[N];
__device__ int   g_cnt[NLEV];
__device__ int   g_cur[NLEV];
__device__ int   g_off[NLEV + 1];
__device__ int   g_done[NLEV * 256];

__device__ __forceinline__ float sigmoidf_(float x) {
    return 1.0f / (1.0f + expf(-x));
}

// ---------------- asm helpers ----------------
__device__ __forceinline__ uint32_t sptr(const void* p) {
    return (uint32_t)__cvta_generic_to_shared(p);
}
__device__ __forceinline__ void ldsm_x4(uint32_t* r, uint32_t addr) {
    asm volatile("ldmatrix.sync.aligned.m8n8.x4.shared.b16 {%0,%1,%2,%3}, [%4];"
                 : "=r"(r[0]), "=r"(r[1]), "=r"(r[2]), "=r"(r[3]) : "r"(addr));
}
__device__ __forceinline__ void ldsm_x4_t(uint32_t* r, uint32_t addr) {
    asm volatile("ldmatrix.sync.aligned.m8n8.x4.trans.shared.b16 {%0,%1,%2,%3}, [%4];"
                 : "=r"(r[0]), "=r"(r[1]), "=r"(r[2]), "=r"(r[3]) : "r"(addr));
}
__device__ __forceinline__ void mma_bf16(float* c, const uint32_t* a,
                                         uint32_t b0, uint32_t b1) {
    asm volatile("mma.sync.aligned.m16n8k16.row.col.f32.bf16.bf16.f32 "
                 "{%0,%1,%2,%3}, {%4,%5,%6,%7}, {%8,%9}, {%0,%1,%2,%3};"
                 : "+f"(c[0]), "+f"(c[1]), "+f"(c[2]), "+f"(c[3])
                 : "r"(a[0]), "r"(a[1]), "r"(a[2]), "r"(a[3]), "r"(b0), "r"(b1));
}
__device__ __forceinline__ void split2(float x, float y, uint32_t& hi, uint32_t& lo) {
    __nv_bfloat162 h = __floats2bfloat162_rn(x, y);
    float rx = x - __bfloat162float(h.x);
    float ry = y - __bfloat162float(h.y);
    __nv_bfloat162 l = __floats2bfloat162_rn(rx, ry);
    union { __nv_bfloat162 h; uint32_t u; } ch, cl;
    ch.h = h; cl.h = l;
    hi = ch.u; lo = cl.u;
}
__device__ __forceinline__ void cp_async16(uint32_t dst, const void* src) {
    asm volatile("cp.async.ca.shared.global [%0], [%1], 16;" :: "r"(dst), "l"(src));
}
#define CP_COMMIT() asm volatile("cp.async.commit_group;")
#define CP_WAIT1()  asm volatile("cp.async.wait_group 1;")

#define MMA3(ACC, AHI, ALO, BH0, BH1, BL0, BL1) \
    do { mma_bf16(ACC, AHI, BH0, BH1); mma_bf16(ACC, AHI, BL0, BL1); \
         mma_bf16(ACC, ALO, BH0, BH1); } while (0)

// ---------------- bookkeeping ----------------
__global__ void k_setup() {
    int idx = blockIdx.x * blockDim.x + threadIdx.x;
    if (blockIdx.x == 0) {
        if (threadIdx.x < NLEV) { g_cnt[threadIdx.x] = 0; g_cur[threadIdx.x] = 0; }
        for (int i = threadIdx.x; i < NLEV * 256; i += 256) g_done[i] = 0;
    }
    const int NH4 = (N * HID) / 4;
    const int HB4 = (N * HID) / 8;
    float4 z = make_float4(0.f, 0.f, 0.f, 0.f);
    if (idx < NH4)                 ((float4*)g_hs )[idx]             = z;
    else if (idx < NH4 + HB4)      ((float4*)g_hbh)[idx - NH4]       = z;
    else if (idx < NH4 + 2 * HB4)  ((float4*)g_hbl)[idx - NH4 - HB4] = z;
}

__global__ void k_hist(const int* __restrict__ level) {
    int i = blockIdx.x * blockDim.x + threadIdx.x;
    if (i < N) atomicAdd(&g_cnt[level[i]], 1);
}

__global__ void k_scanscatter(const int* __restrict__ level) {
    int t = threadIdx.x;
    if (t == 0) {
        g_off[0] = 0;
        for (int l = 0; l < NLEV; l++) g_off[l + 1] = g_off[l] + g_cnt[l];
    }
    __syncthreads();
    for (int i = t; i < N; i += blockDim.x) {
        int lv = level[i];
        int p  = atomicAdd(&g_cur[lv], 1);
        g_order[g_off[lv] + p] = i;
    }
}

// ---------------- loaders (128 threads) ----------------
__device__ __forceinline__ void load_A_gather(float4* ar, const float* __restrict__ src,
                                              const int* shRows, int t, int k0) {
    #pragma unroll
    for (int i = 0; i < 8; i++) {
        int u = t + i * 128, r = u >> 4, kq = u & 15;
        int grow = shRows[r];
        float4 v = make_float4(0.f, 0.f, 0.f, 0.f);
        if (grow >= 0) v = *(const float4*)(src + (size_t)grow * N + k0 + kq * 4);
        ar[i] = v;
    }
}
__device__ __forceinline__ void load_A_dense(float4* ar, const float* __restrict__ src,
                                             int rowbase, int t, int k0) {
    #pragma unroll
    for (int i = 0; i < 8; i++) {
        int u = t + i * 128, r = u >> 4, kq = u & 15;
        int k = k0 + kq * 4;
        float4 v = make_float4(0.f, 0.f, 0.f, 0.f);
        const float* p = src + (size_t)(rowbase + r) * IN_DIM + k;
        if (k + 3 < IN_DIM) v = *(const float4*)p;
        else if (k < IN_DIM) {
            float tmp[4] = {0.f, 0.f, 0.f, 0.f};
            #pragma unroll
            for (int m = 0; m < 4; m++) if (k + m < IN_DIM) tmp[m] = p[m];
            v = make_float4(tmp[0], tmp[1], tmp[2], tmp[3]);
        }
        ar[i] = v;
    }
}
__device__ __forceinline__ void load_E(float4* er, const float* __restrict__ Ew,
                                       int t, int k0) {
    #pragma unroll
    for (int i = 0; i < 8; i++) {
        int u = t + i * 128, kr = u >> 4, kq = u & 15;
        int k = k0 + kr;
        float4 v = make_float4(0.f, 0.f, 0.f, 0.f);
        if (k < IN_DIM) v = *(const float4*)&Ew[(size_t)k * HID + kq * 4];
        er[i] = v;
    }
}
// cp.async the (already split) h tiles straight to smem stage buffer
__device__ __forceinline__ void cp_H(unsigned char* sraw, int buf, int t, int k0) {
    __nv_bfloat16 (*bh)[HID + 8] =
        (__nv_bfloat16(*)[HID + 8])(sraw + OFF_B + buf * BUF_STRIDE);
    __nv_bfloat16 (*bl)[HID + 8] =
        (__nv_bfloat16(*)[HID + 8])(sraw + OFF_B + buf * BUF_STRIDE + 9216);
    #pragma unroll
    for (int i = 0; i < 4; i++) {
        int u = t + i * 128, kr = u >> 3, q = u & 7;
        size_t gi = (size_t)(k0 + kr) * HID + q * 8;
        cp_async16(sptr(&bh[kr][q * 8]), &g_hbh[gi]);
        cp_async16(sptr(&bl[kr][q * 8]), &g_hbl[gi]);
    }
}
// STS of split A tile from register prefetch
__device__ __forceinline__ void sts_A(unsigned char* sraw, const float4* ar, int t) {
    __nv_bfloat16 (*shAh)[KT + 8] = (__nv_bfloat16(*)[KT + 8])(sraw + OFF_AH);
    __nv_bfloat16 (*shAl)[KT + 8] = (__nv_bfloat16(*)[KT + 8])(sraw + OFF_AL);
    #pragma unroll
    for (int i = 0; i < 8; i++) {
        int u = t + i * 128, r = u >> 4, kq = u & 15;
        uint32_t h0, l0, h1, l1;
        split2(ar[i].x, ar[i].y, h0, l0);
        split2(ar[i].z, ar[i].w, h1, l1);
        *(uint2*)&shAh[r][kq * 4] = make_uint2(h0, h1);
        *(uint2*)&shAl[r][kq * 4] = make_uint2(l0, l1);
    }
}

// ---------------- MMA inner stage (warp tile 32x32) ----------------
__device__ __forceinline__ void mma_stage(float acc[2][4][4], uint32_t aAddrH,
                                          uint32_t aAddrL, uint32_t bAddrH,
                                          uint32_t bAddrL) {
    #pragma unroll
    for (int ks = 0; ks < KT / 16; ks++) {
        uint32_t ah[2][4], al[2][4];
        ldsm_x4(ah[0], aAddrH + ks * 32);
        ldsm_x4(ah[1], aAddrH + 16 * A_ROW + ks * 32);
        ldsm_x4(al[0], aAddrL + ks * 32);
        ldsm_x4(al[1], aAddrL + 16 * A_ROW + ks * 32);
        uint32_t bh0[4], bl0[4], bh1[4], bl1[4];
        ldsm_x4_t(bh0, bAddrH + ks * 16 * B_ROW);
        ldsm_x4_t(bl0, bAddrL + ks * 16 * B_ROW);
        ldsm_x4_t(bh1, bAddrH + ks * 16 * B_ROW + 32);
        ldsm_x4_t(bl1, bAddrL + ks * 16 * B_ROW + 32);
        #pragma unroll
        for (int mt = 0; mt < 2; mt++) {
            MMA3(acc[mt][0], ah[mt], al[mt], bh0[0], bh0[1], bl0[0], bl0[1]);
            MMA3(acc[mt][1], ah[mt], al[mt], bh0[2], bh0[3], bl0[2], bl0[3]);
            MMA3(acc[mt][2], ah[mt], al[mt], bh1[0], bh1[1], bl1[0], bl1[1]);
            MMA3(acc[mt][3], ah[mt], al[mt], bh1[2], bh1[3], bl1[2], bl1[3]);
        }
    }
}

// ---------------- GRU for 32 rows, 128 threads (smem reused) ----------------
__device__ void gru32(const float* __restrict__ Ur, const float* __restrict__ Uz,
                      const float* __restrict__ Uh, const int* __restrict__ rows32,
                      unsigned char* sraw)
{
    float (*shU) [66] = (float(*)[66])(sraw + GR_U);
    float (*shHs)[66] = (float(*)[66])(sraw + GR_HS);
    float (*shRh)[66] = (float(*)[66])(sraw + GR_RH);
    int t = threadIdx.x;
    int c = t & 63, rg = t >> 6;

    #pragma unroll
    for (int i = 0; i < 16; i++) {
        int u = t + i * 128, r = u >> 6, cc = u & 63;
        int gr = rows32[r];
        shHs[r][cc] = (gr >= 0) ? g_hs[(size_t)gr * HID + cc] : 0.0f;
    }
    #pragma unroll
    for (int i = 0; i < 32; i++) { int u = t + i * 128; shU[u >> 6][u & 63] = Ur[u]; }
    __syncthreads();

    float zv[16];

    #pragma unroll
    for (int i = 0; i < 16; i++) {
        int r = rg + 2 * i;
        int gr = rows32[r];
        float s = 0.f;
        #pragma unroll 16
        for (int kk = 0; kk < HID; kk++) s += shHs[r][kk] * shU[kk][c];
        float rj = (gr >= 0) ? sigmoidf_(g_xr[(size_t)gr * HID + c] + s) : 0.0f;
        shRh[r][c] = rj * shHs[r][c];
    }
    __syncthreads();
    #pragma unroll
    for (int i = 0; i < 32; i++) { int u = t + i * 128; shU[u >> 6][u & 63] = Uz[u]; }
    __syncthreads();

    #pragma unroll
    for (int i = 0; i < 16; i++) {
        int r = rg + 2 * i;
        int gr = rows32[r];
        float s = 0.f;
        #pragma unroll 16
        for (int kk = 0; kk < HID; kk++) s += shHs[r][kk] * shU[kk][c];
        zv[i] = (gr >= 0) ? sigmoidf_(g_xz[(size_t)gr * HID + c] + s) : 0.0f;
    }
    __syncthreads();
    #pragma unroll
    for (int i = 0; i < 32; i++) { int u = t + i * 128; shU[u >> 6][u & 63] = Uh[u]; }
    __syncthreads();

    #pragma unroll
    for (int i = 0; i < 16; i++) {
        int r = rg + 2 * i;
        int gr = rows32[r];
        if (gr < 0) continue;
        float s = 0.f;
        #pragma unroll 16
        for (int kk = 0; kk < HID; kk++) s += shRh[r][kk] * shU[kk][c];
        float hh = tanhf(g_xh[(size_t)gr * HID + c] + s);
        float hj = (1.0f - zv[i]) * shHs[r][c] + zv[i] * hh;
        size_t idx = (size_t)gr * HID + c;
        g_h[idx] = hj;
        __nv_bfloat16 bh = __float2bfloat16(hj);
        g_hbh[idx] = bh;
        g_hbl[idx] = __float2bfloat16(hj - __bfloat162float(bh));
    }
}

// ---------------- agg body (persistent tiles, fused gru option) ----------------
__device__ void agg_body(const float* __restrict__ adj,
                         const float* __restrict__ Ur, const float* __restrict__ Uz,
                         const float* __restrict__ Uh,
                         int j, bool fuse_gru,
                         unsigned char* sraw, int bid, int nblk)
{
    int* shRows = (int*)(sraw + OFF_ROWS);
    int* shFlag = (int*)(sraw + OFF_FLAG);

    int cnt = g_cnt[j];
    int off = g_off[j];
    int nRow = (cnt + RROWS - 1) / RROWS;
    int ntile = nRow * KSPLIT;
    int t = threadIdx.x;

    int lane = t & 31;
    int w  = t >> 5;
    int wm = w & 1;
    int wn = w >> 1;
    uint32_t smemBase = sptr(sraw);
    uint32_t aRel = (uint32_t)((wm * 32 + (lane & 15)) * A_ROW + (((lane >> 4) << 3) << 1));
    uint32_t bRel = (uint32_t)((lane & 15) * B_ROW + ((wn * 32 + ((lane >> 4) << 3)) << 1));
    int g = lane >> 2, tq = lane & 3;

    for (int tile = bid; tile < ntile; tile += nblk) {
        int rbi = tile % nRow;
        int ks  = tile / nRow;
        int rb  = rbi * RROWS;
        int kbase = ks * KCHUNK;

        __syncthreads();
        if (t < RROWS) shRows[t] = (rb + t < cnt) ? g_order[off + rb + t] : -1;
        __syncthreads();

        cp_H(sraw, 0, t, kbase);
        CP_COMMIT();

        float4 ar[8];
        load_A_gather(ar, adj, shRows, t, kbase);

        float acc[2][4][4] = {};

        for (int s = 0; s < STAGES_A; s++) {
            if (s > 0) __syncthreads();          // tile-start syncs cover s==0
            sts_A(sraw, ar, t);
            if (s + 1 < STAGES_A) cp_H(sraw, (s + 1) & 1, t, kbase + (s + 1) * KT);
            CP_COMMIT();
            CP_WAIT1();
            __syncthreads();
            if (s + 1 < STAGES_A)
                load_A_gather(ar, adj, shRows, t, kbase + (s + 1) * KT);
            uint32_t bBase = smemBase + OFF_B + (uint32_t)((s & 1) * BUF_STRIDE);
            mma_stage(acc, smemBase + OFF_AH + aRel, smemBase + OFF_AL + aRel,
                      bBase + bRel, bBase + 9216 + bRel);
        }

        // split-K partial accumulate
        #pragma unroll
        for (int mt = 0; mt < 2; mt++) {
            #pragma unroll
            for (int nb = 0; nb < 4; nb++) {
                int col = wn * 32 + nb * 8 + tq * 2;
                int r0 = wm * 32 + mt * 16 + g;
                int gr0 = shRows[r0];
                if (gr0 >= 0) {
                    atomicAdd(&g_hs[(size_t)gr0 * HID + col],     acc[mt][nb][0]);
                    atomicAdd(&g_hs[(size_t)gr0 * HID + col + 1], acc[mt][nb][1]);
                }
                int gr1 = shRows[r0 + 8];
                if (gr1 >= 0) {
                    atomicAdd(&g_hs[(size_t)gr1 * HID + col],     acc[mt][nb][2]);
                    atomicAdd(&g_hs[(size_t)gr1 * HID + col + 1], acc[mt][nb][3]);
                }
            }
        }

        if (fuse_gru) {
            __threadfence();
            if (t == 0) {
                int done = atomicAdd(&g_done[j * 256 + rbi], 1);
                *shFlag = (done == KSPLIT - 1);
            }
            __syncthreads();
            if (*shFlag) {
                __threadfence();
                gru32(Ur, Uz, Uh, shRows,      sraw);
                __syncthreads();
                gru32(Ur, Uz, Uh, shRows + 32, sraw);
            }
        }
    }
}

// ---------------- embed body ----------------
__device__ void embed_body(const float* __restrict__ tfidf, const float* __restrict__ Ew,
                           const float* __restrict__ Wr, const float* __restrict__ Wz,
                           const float* __restrict__ Wh,
                           unsigned char* sraw, int rowblock)
{
    __nv_bfloat16 (*shBh)[HID + 8] = (__nv_bfloat16(*)[HID + 8])(sraw + OFF_B);
    __nv_bfloat16 (*shBl)[HID + 8] = (__nv_bfloat16(*)[HID + 8])(sraw + OFF_B + 9216);
    float (*shX)[68] = (float(*)[68])(sraw);            // 17408 B over A region
    float (*shW)[64] = (float(*)[64])(sraw + OFF_B);    // 16384 B over B region

    int t = threadIdx.x;
    int rowbase = rowblock * RROWS;

    int lane = t & 31;
    int w  = t >> 5;
    int wm = w & 1;
    int wn = w >> 1;
    uint32_t smemBase = sptr(sraw);
    uint32_t aRel = (uint32_t)((wm * 32 + (lane & 15)) * A_ROW + (((lane >> 4) << 3) << 1));
    uint32_t bRel = (uint32_t)((lane & 15) * B_ROW + ((wn * 32 + ((lane >> 4) << 3)) << 1));

    float4 ar[8], er[8];
    load_A_dense(ar, tfidf, rowbase, t, 0);
    load_E(er, Ew, t, 0);

    float acc[2][4][4] = {};

    for (int s = 0; s < STAGES_E; s++) {
        __syncthreads();
        sts_A(sraw, ar, t);
        #pragma unroll
        for (int i = 0; i < 8; i++) {
            int u = t + i * 128, kr = u >> 4, kq = u & 15;
            uint32_t h0, l0, h1, l1;
            split2(er[i].x, er[i].y, h0, l0);
            split2(er[i].z, er[i].w, h1, l1);
            *(uint2*)&shBh[kr][kq * 4] = make_uint2(h0, h1);
            *(uint2*)&shBl[kr][kq * 4] = make_uint2(l0, l1);
        }
        __syncthreads();
        if (s + 1 < STAGES_E) {
            load_A_dense(ar, tfidf, rowbase, t, (s + 1) * KT);
            load_E(er, Ew, t, (s + 1) * KT);
        }
        mma_stage(acc, smemBase + OFF_AH + aRel, smemBase + OFF_AL + aRel,
                  smemBase + OFF_B + bRel, smemBase + OFF_B + 9216 + bRel);
    }

    __syncthreads();
    // x_hat fragments -> shX (fp32)
    int g = lane >> 2, tq = lane & 3;
    #pragma unroll
    for (int mt = 0; mt < 2; mt++) {
        #pragma unroll
        for (int nb = 0; nb < 4; nb++) {
            int col = wn * 32 + nb * 8 + tq * 2;
            int r0 = wm * 32 + mt * 16 + g;
            shX[r0][col]         = acc[mt][nb][0];
            shX[r0][col + 1]     = acc[mt][nb][1];
            shX[r0 + 8][col]     = acc[mt][nb][2];
            shX[r0 + 8][col + 1] = acc[mt][nb][3];
        }
    }

    const float* Ws[3] = {Wr, Wz, Wh};
    float*       Os[3] = {g_xr, g_xz, g_xh};
    int cq = t & 15, rq = t >> 4;          // 8 x 16 thread grid
    int c0 = cq * 4, r0 = rq * 8;
    #pragma unroll
    for (int wI = 0; wI < 3; wI++) {
        __syncthreads();
        #pragma unroll
        for (int i = 0; i < 8; i++) {
            int u = t + i * 128;
            int kk = u >> 4, c4 = (u & 15) * 4;
            *(float4*)&shW[kk][c4] = *(const float4*)&Ws[wI][(size_t)kk * HID + c4];
        }
        __syncthreads();
        float o[8][4] = {};
        #pragma unroll 16
        for (int kk = 0; kk < HID; kk++) {
            float4 b = *(float4*)&shW[kk][c0];
            #pragma unroll
            for (int i = 0; i < 8; i++) {
                float a = shX[r0 + i][kk];
                o[i][0] += a * b.x; o[i][1] += a * b.y;
                o[i][2] += a * b.z; o[i][3] += a * b.w;
            }
        }
        #pragma unroll
        for (int i = 0; i < 8; i++)
            *(float4*)&Os[wI][(size_t)(rowbase + r0 + i) * HID + c0] =
                make_float4(o[i][0], o[i][1], o[i][2], o[i][3]);
    }
}

// ---------------- kernels ----------------
__global__ __launch_bounds__(THREADS, 4) void fat_kernel(
    const float* __restrict__ adj, const float* __restrict__ tfidf,
    const float* __restrict__ Ew, const float* __restrict__ Wr,
    const float* __restrict__ Wz, const float* __restrict__ Wh)
{
    extern __shared__ __align__(16) unsigned char sraw[];
    int bx = blockIdx.x;
    if (bx < AGG_BLKS)
        agg_body(adj, 0, 0, 0, NLEV - 1, false, sraw, bx, AGG_BLKS);
    else
        embed_body(tfidf, Ew, Wr, Wz, Wh, sraw, bx - AGG_BLKS);
}

__global__ __launch_bounds__(THREADS, 4) void aggru_kernel(
    const float* __restrict__ adj, const float* __restrict__ Ur,
    const float* __restrict__ Uz, const float* __restrict__ Uh, int j)
{
    extern __shared__ __align__(16) unsigned char sraw[];
    agg_body(adj, Ur, Uz, Uh, j, true, sraw, blockIdx.x, AGG_BLKS);
}

__global__ __launch_bounds__(THREADS) void gru_kernel(
    const float* __restrict__ Ur, const float* __restrict__ Uz,
    const float* __restrict__ Uh, int j)
{
    __shared__ __align__(16) unsigned char sraw[33920];
    int* shRows = (int*)(sraw + 33792);
    int cnt = g_cnt[j];
    int off = g_off[j];
    int ntile = (cnt + 31) >> 5;
    int t = threadIdx.x;
    for (int tile = blockIdx.x; tile < ntile; tile += GRU_BLKS) {
        int rb = tile * 32;
        __syncthreads();
        if (t < 32) shRows[t] = (rb + t < cnt) ? g_order[off + rb + t] : -1;
        __syncthreads();
        gru32(Ur, Uz, Uh, shRows, sraw);
    }
}

__global__ void final_kernel(const float* __restrict__ dec_w,
                             const float* __restrict__ dec_b,
                             float* __restrict__ out)
{
    __shared__ float red[4][HID];
    __shared__ float root[HID];
    int t = threadIdx.x;
    int c = t & 63, q = t >> 6;
    int cnt = g_cnt[0], off = g_off[0];
    float s = 0.f;
    for (int l = q; l < cnt; l += 4) {
        int gr = g_order[off + l];
        s += g_h[(size_t)gr * HID + c];
    }
    red[q][c] = s;
    __syncthreads();
    if (t < HID) root[t] = red[0][t] + red[1][t] + red[2][t] + red[3][t];
    __syncthreads();
    if (t < NCLS) {
        float a = dec_b[t];
        #pragma unroll 16
        for (int k = 0; k < HID; k++) a += root[k] * dec_w[k * NCLS + t];
        out[t] = a;
    }
}

// ---------------- launch ----------------
extern "C" void kernel_launch(void* const* d_in, const int* in_sizes, int n_in,
                              void* d_out, int out_size)
{
    const float* adj   = (const float*)d_in[0];
    const float* tfidf = (const float*)d_in[1];
    const int*   level = (const int*)d_in[2];
    const float* Ew    = (const float*)d_in[3];
    const float* Wr    = (const float*)d_in[4];
    const float* Wz    = (const float*)d_in[5];
    const float* Ur    = (const float*)d_in[6];
    const float* Uz    = (const float*)d_in[7];
    const float* Wh    = (const float*)d_in[8];
    const float* Uh    = (const float*)d_in[9];
    const float* dw    = (const float*)d_in[10];
    const float* db    = (const float*)d_in[11];
    float* out = (float*)d_out;

    cudaFuncSetAttribute(fat_kernel,   cudaFuncAttributeMaxDynamicSharedMemorySize, SMEM_AGG);
    cudaFuncSetAttribute(aggru_kernel, cudaFuncAttributeMaxDynamicSharedMemorySize, SMEM_AGG);

    k_setup<<<2048, 256>>>();
    k_hist<<<64, 256>>>(level);
    k_scanscatter<<<1, 1024>>>(level);
    // index 3: agg(level 10) + embed fused
    fat_kernel<<<AGG_BLKS + EMB_BLKS, THREADS, SMEM_AGG>>>(adj, tfidf, Ew, Wr, Wz, Wh);
    gru_kernel<<<GRU_BLKS, THREADS>>>(Ur, Uz, Uh, NLEV - 1);
    for (int j = NLEV - 2; j >= 0; j--)
        aggru_kernel<<<AGG_BLKS, THREADS, SMEM_AGG>>>(adj, Ur, Uz, Uh, j);
    final_kernel<<<1, 256>>>(dw, db, out);
}

// round 12
// speedup vs baseline: 1.8807x; 1.8807x over previous
#include <cuda_runtime.h>
#include <cuda_bf16.h>
#include <math.h>
#include <stdint.h>

#define N       16384
#define IN_DIM  5000
#define HID     64
#define NCLS    4
#define NLEV    11
#define KSPLIT  32
#define KCHUNK  (N / KSPLIT)               /* 512 */
#define KT      64
#define STAGES_A (KCHUNK / KT)             /* 8 */
#define STAGES_E ((IN_DIM + KT - 1) / KT)  /* 79 */
#define RROWS   128
#define THREADS 256
#define AGG_BLKS 384
#define GRU_BLKS 128
#define EMB_BLKS (N / RROWS)               /* 128 */

// dynamic smem layout (bytes)
#define OFF_AH   0                          /* 128 x 72 bf16 = 18432 */
#define OFF_AL   18432
#define OFF_BH   36864                      /* 64 x 72 bf16 = 9216 */
#define OFF_BL   46080
#define OFF_ROWS 55296                      /* 128 ints */
#define SMEM_DYN 55824

#define A_ROW 144                           /* (KT+8)*2 bytes */
#define B_ROW 144                           /* (HID+8)*2 bytes */

// ---------------- device scratch ----------------
__device__ float g_h  [N * HID];
__device__ float g_hs [N * HID];
__device__ float g_xr [N * HID];
__device__ float g_xz [N * HID];
__device__ float g_xh [N * HID];
__device__ __nv_bfloat16 g_hbh[N * HID];
__device__ __nv_bfloat16 g_hbl[N * HID];
__device__ int   g_order[N];
__device__ int   g_cnt[NLEV];
__device__ int   g_cur[NLEV];
__device__ int   g_off[NLEV + 1];

__device__ __forceinline__ float sigmoidf_(float x) {
    return 1.0f / (1.0f + expf(-x));
}

// ---------------- asm helpers ----------------
__device__ __forceinline__ uint32_t sptr(const void* p) {
    return (uint32_t)__cvta_generic_to_shared(p);
}
__device__ __forceinline__ void ldsm_x4(uint32_t* r, uint32_t addr) {
    asm volatile("ldmatrix.sync.aligned.m8n8.x4.shared.b16 {%0,%1,%2,%3}, [%4];"
                 : "=r"(r[0]), "=r"(r[1]), "=r"(r[2]), "=r"(r[3]) : "r"(addr));
}
__device__ __forceinline__ void ldsm_x4_t(uint32_t* r, uint32_t addr) {
    asm volatile("ldmatrix.sync.aligned.m8n8.x4.trans.shared.b16 {%0,%1,%2,%3}, [%4];"
                 : "=r"(r[0]), "=r"(r[1]), "=r"(r[2]), "=r"(r[3]) : "r"(addr));
}
__device__ __forceinline__ void mma_bf16(float* c, const uint32_t* a,
                                         uint32_t b0, uint32_t b1) {
    asm volatile("mma.sync.aligned.m16n8k16.row.col.f32.bf16.bf16.f32 "
                 "{%0,%1,%2,%3}, {%4,%5,%6,%7}, {%8,%9}, {%0,%1,%2,%3};"
                 : "+f"(c[0]), "+f"(c[1]), "+f"(c[2]), "+f"(c[3])
                 : "r"(a[0]), "r"(a[1]), "r"(a[2]), "r"(a[3]), "r"(b0), "r"(b1));
}
__device__ __forceinline__ void split2(float x, float y, uint32_t& hi, uint32_t& lo) {
    __nv_bfloat162 h = __floats2bfloat162_rn(x, y);
    float rx = x - __bfloat162float(h.x);
    float ry = y - __bfloat162float(h.y);
    __nv_bfloat162 l = __floats2bfloat162_rn(rx, ry);
    union { __nv_bfloat162 h; uint32_t u; } ch, cl;
    ch.h = h; cl.h = l;
    hi = ch.u; lo = cl.u;
}

#define MMA3(ACC, AHI, ALO, BH0, BH1, BL0, BL1) \
    do { mma_bf16(ACC, AHI, BH0, BH1); mma_bf16(ACC, AHI, BL0, BL1); \
         mma_bf16(ACC, ALO, BH0, BH1); } while (0)

// ---------------- bookkeeping ----------------
__global__ void k_setup() {
    int idx = blockIdx.x * blockDim.x + threadIdx.x;
    if (blockIdx.x == 0 && threadIdx.x < NLEV) {
        g_cnt[threadIdx.x] = 0; g_cur[threadIdx.x] = 0;
    }
    const int NH4 = (N * HID) / 4;
    const int HB4 = (N * HID) / 8;
    float4 z = make_float4(0.f, 0.f, 0.f, 0.f);
    if (idx < NH4)                 ((float4*)g_hs )[idx]             = z;
    else if (idx < NH4 + HB4)      ((float4*)g_hbh)[idx - NH4]       = z;
    else if (idx < NH4 + 2 * HB4)  ((float4*)g_hbl)[idx - NH4 - HB4] = z;
}

__global__ void k_hist(const int* __restrict__ level) {
    int i = blockIdx.x * blockDim.x + threadIdx.x;
    if (i < N) atomicAdd(&g_cnt[level[i]], 1);
}

__global__ void k_scanscatter(const int* __restrict__ level) {
    int t = threadIdx.x;
    if (t == 0) {
        g_off[0] = 0;
        for (int l = 0; l < NLEV; l++) g_off[l + 1] = g_off[l] + g_cnt[l];
    }
    __syncthreads();
    for (int i = t; i < N; i += blockDim.x) {
        int lv = level[i];
        int p  = atomicAdd(&g_cur[lv], 1);
        g_order[g_off[lv] + p] = i;
    }
}

// ---------------- loaders (256 threads) ----------------
// A tile 128 rows x 64 k fp32 -> 8 float4/thread
__device__ __forceinline__ void load_A_gather(float4* ar, const float* __restrict__ src,
                                              const int* shRows, int t, int k0) {
    #pragma unroll
    for (int i = 0; i < 8; i++) {
        int u = t + i * 256, r = u >> 4, kq = u & 15;
        int grow = shRows[r];
        float4 v = make_float4(0.f, 0.f, 0.f, 0.f);
        if (grow >= 0) v = *(const float4*)(src + (size_t)grow * N + k0 + kq * 4);
        ar[i] = v;
    }
}
__device__ __forceinline__ void load_A_dense(float4* ar, const float* __restrict__ src,
                                             int rowbase, int t, int k0) {
    #pragma unroll
    for (int i = 0; i < 8; i++) {
        int u = t + i * 256, r = u >> 4, kq = u & 15;
        int k = k0 + kq * 4;
        float4 v = make_float4(0.f, 0.f, 0.f, 0.f);
        const float* p = src + (size_t)(rowbase + r) * IN_DIM + k;
        if (k + 3 < IN_DIM) v = *(const float4*)p;
        else if (k < IN_DIM) {
            float tmp[4] = {0.f, 0.f, 0.f, 0.f};
            #pragma unroll
            for (int m = 0; m < 4; m++) if (k + m < IN_DIM) tmp[m] = p[m];
            v = make_float4(tmp[0], tmp[1], tmp[2], tmp[3]);
        }
        ar[i] = v;
    }
}
// h (pre-split bf16) 64 k x 64 c -> 2 uint4/thread each
__device__ __forceinline__ void load_H(uint4* hh, uint4* hl, int t, int k0) {
    #pragma unroll
    for (int i = 0; i < 2; i++) {
        int u = t + i * 256, kr = u >> 3, q = u & 7;
        size_t idx = (size_t)(k0 + kr) * HID + q * 8;
        hh[i] = *(const uint4*)&g_hbh[idx];
        hl[i] = *(const uint4*)&g_hbl[idx];
    }
}
// E tile 64 k x 64 c fp32 -> 4 float4/thread
__device__ __forceinline__ void load_E(float4* er, const float* __restrict__ Ew,
                                       int t, int k0) {
    #pragma unroll
    for (int i = 0; i < 4; i++) {
        int u = t + i * 256, kr = u >> 4, kq = u & 15;
        int k = k0 + kr;
        float4 v = make_float4(0.f, 0.f, 0.f, 0.f);
        if (k < IN_DIM) v = *(const float4*)&Ew[(size_t)k * HID + kq * 4];
        er[i] = v;
    }
}
// STS of split A tile (128 x 64)
__device__ __forceinline__ void sts_A(unsigned char* sraw, const float4* ar, int t) {
    __nv_bfloat16 (*shAh)[KT + 8] = (__nv_bfloat16(*)[KT + 8])(sraw + OFF_AH);
    __nv_bfloat16 (*shAl)[KT + 8] = (__nv_bfloat16(*)[KT + 8])(sraw + OFF_AL);
    #pragma unroll
    for (int i = 0; i < 8; i++) {
        int u = t + i * 256, r = u >> 4, kq = u & 15;
        uint32_t h0, l0, h1, l1;
        split2(ar[i].x, ar[i].y, h0, l0);
        split2(ar[i].z, ar[i].w, h1, l1);
        *(uint2*)&shAh[r][kq * 4] = make_uint2(h0, h1);
        *(uint2*)&shAl[r][kq * 4] = make_uint2(l0, l1);
    }
}

// ---------------- MMA stage: warp tile 32x32 over block tile 128x64 ----------------
__device__ __forceinline__ void mma_stage(float acc[2][4][4], uint32_t aAddrH,
                                          uint32_t aAddrL, uint32_t bAddrH,
                                          uint32_t bAddrL) {
    #pragma unroll
    for (int ks = 0; ks < KT / 16; ks++) {
        uint32_t ah[2][4], al[2][4];
        ldsm_x4(ah[0], aAddrH + ks * 32);
        ldsm_x4(ah[1], aAddrH + 16 * A_ROW + ks * 32);
        ldsm_x4(al[0], aAddrL + ks * 32);
        ldsm_x4(al[1], aAddrL + 16 * A_ROW + ks * 32);
        uint32_t bh0[4], bl0[4], bh1[4], bl1[4];
        ldsm_x4_t(bh0, bAddrH + ks * 16 * B_ROW);
        ldsm_x4_t(bl0, bAddrL + ks * 16 * B_ROW);
        ldsm_x4_t(bh1, bAddrH + ks * 16 * B_ROW + 32);
        ldsm_x4_t(bl1, bAddrL + ks * 16 * B_ROW + 32);
        #pragma unroll
        for (int mt = 0; mt < 2; mt++) {
            MMA3(acc[mt][0], ah[mt], al[mt], bh0[0], bh0[1], bl0[0], bl0[1]);
            MMA3(acc[mt][1], ah[mt], al[mt], bh0[2], bh0[3], bl0[2], bl0[3]);
            MMA3(acc[mt][2], ah[mt], al[mt], bh1[0], bh1[1], bl1[0], bl1[1]);
            MMA3(acc[mt][3], ah[mt], al[mt], bh1[2], bh1[3], bl1[2], bl1[3]);
        }
    }
}

// ---------------- agg body ----------------
__device__ void agg_body(const float* __restrict__ adj, int j,
                         unsigned char* sraw, int bid, int nblk)
{
    int* shRows = (int*)(sraw + OFF_ROWS);

    int cnt = g_cnt[j];
    int off = g_off[j];
    int nRow = (cnt + RROWS - 1) / RROWS;
    int ntile = nRow * KSPLIT;
    int t = threadIdx.x;

    int lane = t & 31;
    int w  = t >> 5;
    int wm = w & 3;               // 4 m-groups of 32 rows
    int wn = w >> 2;              // 2 n-groups of 32 cols
    uint32_t smemBase = sptr(sraw);
    uint32_t aRel = (uint32_t)((wm * 32 + (lane & 15)) * A_ROW + (((lane >> 4) << 3) << 1));
    uint32_t bRel = (uint32_t)((lane & 15) * B_ROW + ((wn * 32 + ((lane >> 4) << 3)) << 1));
    int g = lane >> 2, tq = lane & 3;

    for (int tile = bid; tile < ntile; tile += nblk) {
        int rbi = tile % nRow;
        int ks  = tile / nRow;
        int rb  = rbi * RROWS;
        int kbase = ks * KCHUNK;

        __syncthreads();
        if (t < RROWS) shRows[t] = (rb + t < cnt) ? g_order[off + rb + t] : -1;
        __syncthreads();

        float4 ar[8];
        uint4  hh[2], hl[2];
        load_A_gather(ar, adj, shRows, t, kbase);
        load_H(hh, hl, t, kbase);

        float acc[2][4][4] = {};

        for (int s = 0; s < STAGES_A; s++) {
            sts_A(sraw, ar, t);
            {
                __nv_bfloat16 (*shBh)[HID + 8] = (__nv_bfloat16(*)[HID + 8])(sraw + OFF_BH);
                __nv_bfloat16 (*shBl)[HID + 8] = (__nv_bfloat16(*)[HID + 8])(sraw + OFF_BL);
                #pragma unroll
                for (int i = 0; i < 2; i++) {
                    int u = t + i * 256, kr = u >> 3, q = u & 7;
                    *(uint4*)&shBh[kr][q * 8] = hh[i];
                    *(uint4*)&shBl[kr][q * 8] = hl[i];
                }
            }
            __syncthreads();
            if (s + 1 < STAGES_A) {
                int k0 = kbase + (s + 1) * KT;
                load_A_gather(ar, adj, shRows, t, k0);
                load_H(hh, hl, t, k0);
            }
            mma_stage(acc, smemBase + OFF_AH + aRel, smemBase + OFF_AL + aRel,
                      smemBase + OFF_BH + bRel, smemBase + OFF_BL + bRel);
            __syncthreads();
        }

        // split-K partial accumulate
        #pragma unroll
        for (int mt = 0; mt < 2; mt++) {
            #pragma unroll
            for (int nb = 0; nb < 4; nb++) {
                int col = wn * 32 + nb * 8 + tq * 2;
                int r0 = wm * 32 + mt * 16 + g;
                int gr0 = shRows[r0];
                if (gr0 >= 0) {
                    atomicAdd(&g_hs[(size_t)gr0 * HID + col],     acc[mt][nb][0]);
                    atomicAdd(&g_hs[(size_t)gr0 * HID + col + 1], acc[mt][nb][1]);
                }
                int gr1 = shRows[r0 + 8];
                if (gr1 >= 0) {
                    atomicAdd(&g_hs[(size_t)gr1 * HID + col],     acc[mt][nb][2]);
                    atomicAdd(&g_hs[(size_t)gr1 * HID + col + 1], acc[mt][nb][3]);
                }
            }
        }
    }
}

// ---------------- embed body (128-row tiles) ----------------
__device__ void embed_body(const float* __restrict__ tfidf, const float* __restrict__ Ew,
                           const float* __restrict__ Wr, const float* __restrict__ Wz,
                           const float* __restrict__ Wh,
                           unsigned char* sraw, int rowblock)
{
    __nv_bfloat16 (*shBh)[HID + 8] = (__nv_bfloat16(*)[HID + 8])(sraw + OFF_BH);
    __nv_bfloat16 (*shBl)[HID + 8] = (__nv_bfloat16(*)[HID + 8])(sraw + OFF_BL);
    float (*shX)[68] = (float(*)[68])(sraw);            // 128x68 f32 = 34816 over A region
    float (*shW)[64] = (float(*)[64])(sraw + OFF_BH);   // 16384 over B region

    int t = threadIdx.x;
    int rowbase = rowblock * RROWS;

    int lane = t & 31;
    int w  = t >> 5;
    int wm = w & 3;
    int wn = w >> 2;
    uint32_t smemBase = sptr(sraw);
    uint32_t aRel = (uint32_t)((wm * 32 + (lane & 15)) * A_ROW + (((lane >> 4) << 3) << 1));
    uint32_t bRel = (uint32_t)((lane & 15) * B_ROW + ((wn * 32 + ((lane >> 4) << 3)) << 1));

    float4 ar[8], er[4];
    load_A_dense(ar, tfidf, rowbase, t, 0);
    load_E(er, Ew, t, 0);

    float acc[2][4][4] = {};

    for (int s = 0; s < STAGES_E; s++) {
        sts_A(sraw, ar, t);
        #pragma unroll
        for (int i = 0; i < 4; i++) {
            int u = t + i * 256, kr = u >> 4, kq = u & 15;
            uint32_t h0, l0, h1, l1;
            split2(er[i].x, er[i].y, h0, l0);
            split2(er[i].z, er[i].w, h1, l1);
            *(uint2*)&shBh[kr][kq * 4] = make_uint2(h0, h1);
            *(uint2*)&shBl[kr][kq * 4] = make_uint2(l0, l1);
        }
        __syncthreads();
        if (s + 1 < STAGES_E) {
            load_A_dense(ar, tfidf, rowbase, t, (s + 1) * KT);
            load_E(er, Ew, t, (s + 1) * KT);
        }
        mma_stage(acc, smemBase + OFF_AH + aRel, smemBase + OFF_AL + aRel,
                  smemBase + OFF_BH + bRel, smemBase + OFF_BL + bRel);
        __syncthreads();
    }

    // x_hat fragments -> shX (fp32)
    int g = lane >> 2, tq = lane & 3;
    #pragma unroll
    for (int mt = 0; mt < 2; mt++) {
        #pragma unroll
        for (int nb = 0; nb < 4; nb++) {
            int col = wn * 32 + nb * 8 + tq * 2;
            int r0 = wm * 32 + mt * 16 + g;
            shX[r0][col]         = acc[mt][nb][0];
            shX[r0][col + 1]     = acc[mt][nb][1];
            shX[r0 + 8][col]     = acc[mt][nb][2];
            shX[r0 + 8][col + 1] = acc[mt][nb][3];
        }
    }

    const float* Ws[3] = {Wr, Wz, Wh};
    float*       Os[3] = {g_xr, g_xz, g_xh};
    int cq = t & 15, rq = t >> 4;          // 16 x 16 thread grid
    int c0 = cq * 4, r0 = rq * 8;
    #pragma unroll
    for (int wI = 0; wI < 3; wI++) {
        __syncthreads();
        #pragma unroll
        for (int i = 0; i < 4; i++) {
            int u = t + i * 256;
            int kk = u >> 4, c4 = (u & 15) * 4;
            *(float4*)&shW[kk][c4] = *(const float4*)&Ws[wI][(size_t)kk * HID + c4];
        }
        __syncthreads();
        float o[8][4] = {};
        #pragma unroll 16
        for (int kk = 0; kk < HID; kk++) {
            float4 b = *(float4*)&shW[kk][c0];
            #pragma unroll
            for (int i = 0; i < 8; i++) {
                float a = shX[r0 + i][kk];
                o[i][0] += a * b.x; o[i][1] += a * b.y;
                o[i][2] += a * b.z; o[i][3] += a * b.w;
            }
        }
        #pragma unroll
        for (int i = 0; i < 8; i++)
            *(float4*)&Os[wI][(size_t)(rowbase + r0 + i) * HID + c0] =
                make_float4(o[i][0], o[i][1], o[i][2], o[i][3]);
    }
}

// ---------------- kernels ----------------
__global__ __launch_bounds__(THREADS, 2) void fat_kernel(
    const float* __restrict__ adj, const float* __restrict__ tfidf,
    const float* __restrict__ Ew, const float* __restrict__ Wr,
    const float* __restrict__ Wz, const float* __restrict__ Wh)
{
    extern __shared__ __align__(16) unsigned char sraw[];
    int bx = blockIdx.x;
    if (bx < AGG_BLKS)
        agg_body(adj, NLEV - 1, sraw, bx, AGG_BLKS);
    else
        embed_body(tfidf, Ew, Wr, Wz, Wh, sraw, bx - AGG_BLKS);
}

__global__ __launch_bounds__(THREADS, 2) void agg_kernel(
    const float* __restrict__ adj, int j)
{
    extern __shared__ __align__(16) unsigned char sraw[];
    agg_body(adj, j, sraw, blockIdx.x, AGG_BLKS);
}

// ---------------- GRU (proven round-8 version) ----------------
__global__ __launch_bounds__(256) void gru_kernel(
    const float* __restrict__ Ur, const float* __restrict__ Uz,
    const float* __restrict__ Uh, int j)
{
    __shared__ float shU [HID][HID + 1];
    __shared__ float shHs[32][HID + 1];
    __shared__ float shRh[32][HID + 1];
    __shared__ int   shRows[32];

    int cnt = g_cnt[j];
    int off = g_off[j];
    int ntile = (cnt + 31) >> 5;
    int t = threadIdx.x;
    int c = t & 63, rg = t >> 6;

    for (int tile = blockIdx.x; tile < ntile; tile += GRU_BLKS) {
        int rb = tile * 32;
        __syncthreads();
        if (t < 32) shRows[t] = (rb + t < cnt) ? g_order[off + rb + t] : -1;
        __syncthreads();

        #pragma unroll
        for (int i = 0; i < 8; i++) {
            int u = t + i * 256;
            int r = u >> 6, cc = u & 63;
            int gr = shRows[r];
            shHs[r][cc] = (gr >= 0) ? g_hs[(size_t)gr * HID + cc] : 0.0f;
        }
        #pragma unroll
        for (int i = 0; i < 16; i++) { int u = t + i * 256; shU[u >> 6][u & 63] = Ur[u]; }
        __syncthreads();

        float zv[8], hsv[8];

        #pragma unroll
        for (int i = 0; i < 8; i++) {
            int r = rg + 4 * i;
            int gr = shRows[r];
            float s = 0.f;
            #pragma unroll 16
            for (int kk = 0; kk < HID; kk++) s += shHs[r][kk] * shU[kk][c];
            float rj = (gr >= 0) ? sigmoidf_(g_xr[(size_t)gr * HID + c] + s) : 0.0f;
            shRh[r][c] = rj * shHs[r][c];
        }
        __syncthreads();
        #pragma unroll
        for (int i = 0; i < 16; i++) { int u = t + i * 256; shU[u >> 6][u & 63] = Uz[u]; }
        __syncthreads();

        #pragma unroll
        for (int i = 0; i < 8; i++) {
            int r = rg + 4 * i;
            int gr = shRows[r];
            float s = 0.f;
            #pragma unroll 16
            for (int kk = 0; kk < HID; kk++) s += shHs[r][kk] * shU[kk][c];
            zv[i]  = (gr >= 0) ? sigmoidf_(g_xz[(size_t)gr * HID + c] + s) : 0.0f;
            hsv[i] = shHs[r][c];
        }
        __syncthreads();
        #pragma unroll
        for (int i = 0; i < 16; i++) { int u = t + i * 256; shU[u >> 6][u & 63] = Uh[u]; }
        __syncthreads();

        #pragma unroll
        for (int i = 0; i < 8; i++) {
            int r = rg + 4 * i;
            int gr = shRows[r];
            if (gr < 0) continue;
            float s = 0.f;
            #pragma unroll 16
            for (int kk = 0; kk < HID; kk++) s += shRh[r][kk] * shU[kk][c];
            float hh = tanhf(g_xh[(size_t)gr * HID + c] + s);
            float hj = (1.0f - zv[i]) * hsv[i] + zv[i] * hh;
            size_t idx = (size_t)gr * HID + c;
            g_h[idx] = hj;
            __nv_bfloat16 bh = __float2bfloat16(hj);
            g_hbh[idx] = bh;
            g_hbl[idx] = __float2bfloat16(hj - __bfloat162float(bh));
        }
    }
}

// ---------------- root reduce + decode ----------------
__global__ void final_kernel(const float* __restrict__ dec_w,
                             const float* __restrict__ dec_b,
                             float* __restrict__ out)
{
    __shared__ float red[4][HID];
    __shared__ float root[HID];
    int t = threadIdx.x;
    int c = t & 63, q = t >> 6;
    int cnt = g_cnt[0], off = g_off[0];
    float s = 0.f;
    for (int l = q; l < cnt; l += 4) {
        int gr = g_order[off + l];
        s += g_h[(size_t)gr * HID + c];
    }
    red[q][c] = s;
    __syncthreads();
    if (t < HID) root[t] = red[0][t] + red[1][t] + red[2][t] + red[3][t];
    __syncthreads();
    if (t < NCLS) {
        float a = dec_b[t];
        #pragma unroll 16
        for (int k = 0; k < HID; k++) a += root[k] * dec_w[k * NCLS + t];
        out[t] = a;
    }
}

// ---------------- launch ----------------
extern "C" void kernel_launch(void* const* d_in, const int* in_sizes, int n_in,
                              void* d_out, int out_size)
{
    const float* adj   = (const float*)d_in[0];
    const float* tfidf = (const float*)d_in[1];
    const int*   level = (const int*)d_in[2];
    const float* Ew    = (const float*)d_in[3];
    const float* Wr    = (const float*)d_in[4];
    const float* Wz    = (const float*)d_in[5];
    const float* Ur    = (const float*)d_in[6];
    const float* Uz    = (const float*)d_in[7];
    const float* Wh    = (const float*)d_in[8];
    const float* Uh    = (const float*)d_in[9];
    const float* dw    = (const float*)d_in[10];
    const float* db    = (const float*)d_in[11];
    float* out = (float*)d_out;

    cudaFuncSetAttribute(fat_kernel, cudaFuncAttributeMaxDynamicSharedMemorySize, SMEM_DYN);
    cudaFuncSetAttribute(agg_kernel, cudaFuncAttributeMaxDynamicSharedMemorySize, SMEM_DYN);

    k_setup<<<2048, 256>>>();
    k_hist<<<64, 256>>>(level);
    k_scanscatter<<<1, 1024>>>(level);
    // index 3: agg(level 10) + embed fused
    fat_kernel<<<AGG_BLKS + EMB_BLKS, THREADS, SMEM_DYN>>>(adj, tfidf, Ew, Wr, Wz, Wh);
    gru_kernel<<<GRU_BLKS, 256>>>(Ur, Uz, Uh, NLEV - 1);
    for (int j = NLEV - 2; j >= 0; j--) {
        agg_kernel<<<AGG_BLKS, THREADS, SMEM_DYN>>>(adj, j);
        gru_kernel<<<GRU_BLKS, 256>>>(Ur, Uz, Uh, j);
    }
    final_kernel<<<1, 256>>>(dw, db, out);
}

// round 14
// speedup vs baseline: 1.9856x; 1.0558x over previous
#include <cuda_runtime.h>
#include <cuda_bf16.h>
#include <math.h>
#include <stdint.h>

#define N       16384
#define IN_DIM  5000
#define HID     64
#define NCLS    4
#define NLEV    11
#define KSPLIT  64
#define KCHUNK  (N / KSPLIT)               /* 256 */
#define KT      64
#define STAGES_A (KCHUNK / KT)             /* 4 */
#define STAGES_E ((IN_DIM + KT - 1) / KT)  /* 79 */
#define RROWS   128
#define THREADS 256
#define AGG_BLKS 296
#define EROWS   64
#define EMB_BLKS (N / EROWS)               /* 256 */
#define FIN_BLKS 64

// agg smem layout
#define OFF_AH   0                          /* 128 x 72 bf16 = 18432 */
#define OFF_AL   18432
#define OFF_BH   36864                      /* 64 x 72 bf16 = 9216 */
#define OFF_BL   46080
#define OFF_ROWS 55296                      /* 128 ints */
#define SMEM_DYN 55824
// embed smem layout (64-row A tiles)
#define E_AH 0                              /* 64 x 72 = 9216 */
#define E_AL 9216
#define E_BH 18432
#define E_BL 27648
// gru smem layout
#define G_U    0                            /* 64 x 65 f32 = 16640 */
#define G_HS   16640                        /* 32 x 65 f32 = 8320 */
#define G_RH   24960
#define G_ROWS 33280                        /* 32 ints */

#define A_ROW 144
#define B_ROW 144

// ---------------- device scratch ----------------
__device__ float g_h  [N * HID];
__device__ float g_hs [N * HID];
__device__ float g_xr [N * HID];
__device__ float g_xz [N * HID];
__device__ float g_xh [N * HID];
__device__ __nv_bfloat16 g_hbh[N * HID];
__device__ __nv_bfloat16 g_hbl[N * HID];
__device__ int   g_order[N];
__device__ int   g_cnt[NLEV];
__device__ int   g_cur[NLEV];
__device__ int   g_off[NLEV + 1];
__device__ int   g_done[NLEV];

__device__ __forceinline__ float sigmoidf_(float x) {
    return 1.0f / (1.0f + expf(-x));
}

// ---------------- asm helpers ----------------
__device__ __forceinline__ uint32_t sptr(const void* p) {
    return (uint32_t)__cvta_generic_to_shared(p);
}
__device__ __forceinline__ void ldsm_x4(uint32_t* r, uint32_t addr) {
    asm volatile("ldmatrix.sync.aligned.m8n8.x4.shared.b16 {%0,%1,%2,%3}, [%4];"
                 : "=r"(r[0]), "=r"(r[1]), "=r"(r[2]), "=r"(r[3]) : "r"(addr));
}
__device__ __forceinline__ void ldsm_x4_t(uint32_t* r, uint32_t addr) {
    asm volatile("ldmatrix.sync.aligned.m8n8.x4.trans.shared.b16 {%0,%1,%2,%3}, [%4];"
                 : "=r"(r[0]), "=r"(r[1]), "=r"(r[2]), "=r"(r[3]) : "r"(addr));
}
__device__ __forceinline__ void mma_bf16(float* c, const uint32_t* a,
                                         uint32_t b0, uint32_t b1) {
    asm volatile("mma.sync.aligned.m16n8k16.row.col.f32.bf16.bf16.f32 "
                 "{%0,%1,%2,%3}, {%4,%5,%6,%7}, {%8,%9}, {%0,%1,%2,%3};"
                 : "+f"(c[0]), "+f"(c[1]), "+f"(c[2]), "+f"(c[3])
                 : "r"(a[0]), "r"(a[1]), "r"(a[2]), "r"(a[3]), "r"(b0), "r"(b1));
}
__device__ __forceinline__ void split2(float x, float y, uint32_t& hi, uint32_t& lo) {
    __nv_bfloat162 h = __floats2bfloat162_rn(x, y);
    float rx = x - __bfloat162float(h.x);
    float ry = y - __bfloat162float(h.y);
    __nv_bfloat162 l = __floats2bfloat162_rn(rx, ry);
    union { __nv_bfloat162 h; uint32_t u; } ch, cl;
    ch.h = h; cl.h = l;
    hi = ch.u; lo = cl.u;
}

#define MMA3(ACC, AHI, ALO, BH0, BH1, BL0, BL1) \
    do { mma_bf16(ACC, AHI, BH0, BH1); mma_bf16(ACC, AHI, BL0, BL1); \
         mma_bf16(ACC, ALO, BH0, BH1); } while (0)

// ---------------- bookkeeping ----------------
__global__ void k_setup() {
    int idx = blockIdx.x * blockDim.x + threadIdx.x;
    if (blockIdx.x == 0 && threadIdx.x < NLEV) {
        g_cnt[threadIdx.x] = 0; g_cur[threadIdx.x] = 0; g_done[threadIdx.x] = 0;
    }
    const int NH4 = (N * HID) / 4;
    const int HB4 = (N * HID) / 8;
    float4 z = make_float4(0.f, 0.f, 0.f, 0.f);
    if (idx < NH4)                 ((float4*)g_hs )[idx]             = z;
    else if (idx < NH4 + HB4)      ((float4*)g_hbh)[idx - NH4]       = z;
    else if (idx < NH4 + 2 * HB4)  ((float4*)g_hbl)[idx - NH4 - HB4] = z;
}

__global__ void k_hist(const int* __restrict__ level) {
    int i = blockIdx.x * blockDim.x + threadIdx.x;
    if (i < N) atomicAdd(&g_cnt[level[i]], 1);
}

__global__ void k_scanscatter(const int* __restrict__ level) {
    int t = threadIdx.x;
    if (t == 0) {
        g_off[0] = 0;
        for (int l = 0; l < NLEV; l++) g_off[l + 1] = g_off[l] + g_cnt[l];
    }
    __syncthreads();
    for (int i = t; i < N; i += blockDim.x) {
        int lv = level[i];
        int p  = atomicAdd(&g_cur[lv], 1);
        g_order[g_off[lv] + p] = i;
    }
}

// ---------------- GRU for one 32-row tile (256 threads, smem scratch) ----------------
__device__ void gru32(const float* __restrict__ Ur, const float* __restrict__ Uz,
                      const float* __restrict__ Uh, int cnt, int off, int rb,
                      unsigned char* sraw, bool writeH)
{
    float (*shU )[HID + 1] = (float(*)[HID + 1])(sraw + G_U);
    float (*shHs)[HID + 1] = (float(*)[HID + 1])(sraw + G_HS);
    float (*shRh)[HID + 1] = (float(*)[HID + 1])(sraw + G_RH);
    int* shRows = (int*)(sraw + G_ROWS);
    int t = threadIdx.x;
    int c = t & 63, rg = t >> 6;

    __syncthreads();
    if (t < 32) shRows[t] = (rb + t < cnt) ? g_order[off + rb + t] : -1;
    __syncthreads();

    #pragma unroll
    for (int i = 0; i < 8; i++) {
        int u = t + i * 256, r = u >> 6, cc = u & 63;
        int gr = shRows[r];
        shHs[r][cc] = (gr >= 0) ? g_hs[(size_t)gr * HID + cc] : 0.0f;
    }
    #pragma unroll
    for (int i = 0; i < 16; i++) { int u = t + i * 256; shU[u >> 6][u & 63] = Ur[u]; }
    __syncthreads();

    float zv[8], hsv[8];

    #pragma unroll
    for (int i = 0; i < 8; i++) {
        int r = rg + 4 * i;
        int gr = shRows[r];
        float s = 0.f;
        #pragma unroll 16
        for (int kk = 0; kk < HID; kk++) s += shHs[r][kk] * shU[kk][c];
        float rj = (gr >= 0) ? sigmoidf_(g_xr[(size_t)gr * HID + c] + s) : 0.0f;
        shRh[r][c] = rj * shHs[r][c];
    }
    __syncthreads();
    #pragma unroll
    for (int i = 0; i < 16; i++) { int u = t + i * 256; shU[u >> 6][u & 63] = Uz[u]; }
    __syncthreads();

    #pragma unroll
    for (int i = 0; i < 8; i++) {
        int r = rg + 4 * i;
        int gr = shRows[r];
        float s = 0.f;
        #pragma unroll 16
        for (int kk = 0; kk < HID; kk++) s += shHs[r][kk] * shU[kk][c];
        zv[i]  = (gr >= 0) ? sigmoidf_(g_xz[(size_t)gr * HID + c] + s) : 0.0f;
        hsv[i] = shHs[r][c];
    }
    __syncthreads();
    #pragma unroll
    for (int i = 0; i < 16; i++) { int u = t + i * 256; shU[u >> 6][u & 63] = Uh[u]; }
    __syncthreads();

    #pragma unroll
    for (int i = 0; i < 8; i++) {
        int r = rg + 4 * i;
        int gr = shRows[r];
        if (gr < 0) continue;
        float s = 0.f;
        #pragma unroll 16
        for (int kk = 0; kk < HID; kk++) s += shRh[r][kk] * shU[kk][c];
        float hh = tanhf(g_xh[(size_t)gr * HID + c] + s);
        float hj = (1.0f - zv[i]) * hsv[i] + zv[i] * hh;
        size_t idx = (size_t)gr * HID + c;
        if (writeH) g_h[idx] = hj;
        __nv_bfloat16 bh = __float2bfloat16(hj);
        g_hbh[idx] = bh;
        g_hbl[idx] = __float2bfloat16(hj - __bfloat162float(bh));
    }
}

// ---------------- loaders ----------------
__device__ __forceinline__ void load_A_gather(float4* ar, const float* __restrict__ src,
                                              const int* shRows, int t, int k0) {
    #pragma unroll
    for (int i = 0; i < 8; i++) {
        int u = t + i * 256, r = u >> 4, kq = u & 15;
        int grow = shRows[r];
        float4 v = make_float4(0.f, 0.f, 0.f, 0.f);
        if (grow >= 0) v = *(const float4*)(src + (size_t)grow * N + k0 + kq * 4);
        ar[i] = v;
    }
}
__device__ __forceinline__ void load_A_dense64(float4* ar, const float* __restrict__ src,
                                               int rowbase, int t, int k0) {
    #pragma unroll
    for (int i = 0; i < 4; i++) {
        int u = t + i * 256, r = u >> 4, kq = u & 15;
        int k = k0 + kq * 4;
        float4 v = make_float4(0.f, 0.f, 0.f, 0.f);
        const float* p = src + (size_t)(rowbase + r) * IN_DIM + k;
        if (k + 3 < IN_DIM) v = *(const float4*)p;
        else if (k < IN_DIM) {
            float tmp[4] = {0.f, 0.f, 0.f, 0.f};
            #pragma unroll
            for (int m = 0; m < 4; m++) if (k + m < IN_DIM) tmp[m] = p[m];
            v = make_float4(tmp[0], tmp[1], tmp[2], tmp[3]);
        }
        ar[i] = v;
    }
}
__device__ __forceinline__ void load_H(uint4* hh, uint4* hl, int t, int k0) {
    #pragma unroll
    for (int i = 0; i < 2; i++) {
        int u = t + i * 256, kr = u >> 3, q = u & 7;
        size_t idx = (size_t)(k0 + kr) * HID + q * 8;
        hh[i] = *(const uint4*)&g_hbh[idx];
        hl[i] = *(const uint4*)&g_hbl[idx];
    }
}
__device__ __forceinline__ void load_E(float4* er, const float* __restrict__ Ew,
                                       int t, int k0) {
    #pragma unroll
    for (int i = 0; i < 4; i++) {
        int u = t + i * 256, kr = u >> 4, kq = u & 15;
        int k = k0 + kr;
        float4 v = make_float4(0.f, 0.f, 0.f, 0.f);
        if (k < IN_DIM) v = *(const float4*)&Ew[(size_t)k * HID + kq * 4];
        er[i] = v;
    }
}

// ---------------- agg (128x64 block tile, persistent) ----------------
__device__ void agg_body(const float* __restrict__ adj, int j,
                         unsigned char* sraw, int bid, int nblk)
{
    int* shRows = (int*)(sraw + OFF_ROWS);

    int cnt = g_cnt[j];
    int off = g_off[j];
    int nRow = (cnt + RROWS - 1) / RROWS;
    int ntile = nRow * KSPLIT;
    int t = threadIdx.x;

    int lane = t & 31;
    int w  = t >> 5;
    int wm = w & 3;
    int wn = w >> 2;
    uint32_t smemBase = sptr(sraw);
    uint32_t aRel = (uint32_t)((wm * 32 + (lane & 15)) * A_ROW + (((lane >> 4) << 3) << 1));
    uint32_t bRel = (uint32_t)((lane & 15) * B_ROW + ((wn * 32 + ((lane >> 4) << 3)) << 1));
    int g = lane >> 2, tq = lane & 3;

    for (int tile = bid; tile < ntile; tile += nblk) {
        int rbi = tile % nRow;
        int ks  = tile / nRow;
        int rb  = rbi * RROWS;
        int kbase = ks * KCHUNK;

        __syncthreads();
        if (t < RROWS) shRows[t] = (rb + t < cnt) ? g_order[off + rb + t] : -1;
        __syncthreads();

        float4 ar[8];
        uint4  hh[2], hl[2];
        load_A_gather(ar, adj, shRows, t, kbase);
        load_H(hh, hl, t, kbase);

        float acc[2][4][4] = {};

        for (int s = 0; s < STAGES_A; s++) {
            {   // stage A (split) + B
                __nv_bfloat16 (*shAh)[KT + 8] = (__nv_bfloat16(*)[KT + 8])(sraw + OFF_AH);
                __nv_bfloat16 (*shAl)[KT + 8] = (__nv_bfloat16(*)[KT + 8])(sraw + OFF_AL);
                #pragma unroll
                for (int i = 0; i < 8; i++) {
                    int u = t + i * 256, r = u >> 4, kq = u & 15;
                    uint32_t h0, l0, h1, l1;
                    split2(ar[i].x, ar[i].y, h0, l0);
                    split2(ar[i].z, ar[i].w, h1, l1);
                    *(uint2*)&shAh[r][kq * 4] = make_uint2(h0, h1);
                    *(uint2*)&shAl[r][kq * 4] = make_uint2(l0, l1);
                }
                __nv_bfloat16 (*shBh)[HID + 8] = (__nv_bfloat16(*)[HID + 8])(sraw + OFF_BH);
                __nv_bfloat16 (*shBl)[HID + 8] = (__nv_bfloat16(*)[HID + 8])(sraw + OFF_BL);
                #pragma unroll
                for (int i = 0; i < 2; i++) {
                    int u = t + i * 256, kr = u >> 3, q = u & 7;
                    *(uint4*)&shBh[kr][q * 8] = hh[i];
                    *(uint4*)&shBl[kr][q * 8] = hl[i];
                }
            }
            __syncthreads();
            if (s + 1 < STAGES_A) {
                int k0 = kbase + (s + 1) * KT;
                load_A_gather(ar, adj, shRows, t, k0);
                load_H(hh, hl, t, k0);
            }
            uint32_t aAddrH = smemBase + OFF_AH + aRel;
            uint32_t aAddrL = smemBase + OFF_AL + aRel;
            uint32_t bAddrH = smemBase + OFF_BH + bRel;
            uint32_t bAddrL = smemBase + OFF_BL + bRel;
            #pragma unroll
            for (int kss = 0; kss < KT / 16; kss++) {
                uint32_t ah[2][4], al[2][4];
                ldsm_x4(ah[0], aAddrH + kss * 32);
                ldsm_x4(ah[1], aAddrH + 16 * A_ROW + kss * 32);
                ldsm_x4(al[0], aAddrL + kss * 32);
                ldsm_x4(al[1], aAddrL + 16 * A_ROW + kss * 32);
                uint32_t bh0[4], bl0[4], bh1[4], bl1[4];
                ldsm_x4_t(bh0, bAddrH + kss * 16 * B_ROW);
                ldsm_x4_t(bl0, bAddrL + kss * 16 * B_ROW);
                ldsm_x4_t(bh1, bAddrH + kss * 16 * B_ROW + 32);
                ldsm_x4_t(bl1, bAddrL + kss * 16 * B_ROW + 32);
                #pragma unroll
                for (int mt = 0; mt < 2; mt++) {
                    MMA3(acc[mt][0], ah[mt], al[mt], bh0[0], bh0[1], bl0[0], bl0[1]);
                    MMA3(acc[mt][1], ah[mt], al[mt], bh0[2], bh0[3], bl0[2], bl0[3]);
                    MMA3(acc[mt][2], ah[mt], al[mt], bh1[0], bh1[1], bl1[0], bl1[1]);
                    MMA3(acc[mt][3], ah[mt], al[mt], bh1[2], bh1[3], bl1[2], bl1[3]);
                }
            }
            __syncthreads();
        }

        #pragma unroll
        for (int mt = 0; mt < 2; mt++) {
            #pragma unroll
            for (int nb = 0; nb < 4; nb++) {
                int col = wn * 32 + nb * 8 + tq * 2;
                int r0 = wm * 32 + mt * 16 + g;
                int gr0 = shRows[r0];
                if (gr0 >= 0) {
                    atomicAdd(&g_hs[(size_t)gr0 * HID + col],     acc[mt][nb][0]);
                    atomicAdd(&g_hs[(size_t)gr0 * HID + col + 1], acc[mt][nb][1]);
                }
                int gr1 = shRows[r0 + 8];
                if (gr1 >= 0) {
                    atomicAdd(&g_hs[(size_t)gr1 * HID + col],     acc[mt][nb][2]);
                    atomicAdd(&g_hs[(size_t)gr1 * HID + col + 1], acc[mt][nb][3]);
                }
            }
        }
    }
}

// ---------------- aggru: gru(j+1) prologue + agg(j) ----------------
__global__ __launch_bounds__(THREADS, 2) void aggru_kernel(
    const float* __restrict__ adj, const float* __restrict__ Ur,
    const float* __restrict__ Uz, const float* __restrict__ Uh,
    int j, int prolog)
{
    extern __shared__ __align__(16) unsigned char sraw[];
    int t = threadIdx.x;
    if (prolog) {
        int cntP = g_cnt[j + 1], offP = g_off[j + 1];
        int ntG = (cntP + 31) >> 5;
        if ((int)blockIdx.x < ntG) {
            gru32(Ur, Uz, Uh, cntP, offP, blockIdx.x * 32, sraw, false);
            __threadfence();
            __syncthreads();
            if (t == 0) atomicAdd(&g_done[j + 1], 1);
        }
        if (t == 0) {
            volatile int* p = &g_done[j + 1];
            while (*p < ntG) { }
        }
        __syncthreads();
        __threadfence();
    }
    agg_body(adj, j, sraw, blockIdx.x, AGG_BLKS);
}

// ---------------- embed (64-row tiles) + fused gru(level 10) ----------------
__global__ __launch_bounds__(THREADS, 2) void embed_kernel(
    const float* __restrict__ tfidf, const float* __restrict__ Ew,
    const float* __restrict__ Wr, const float* __restrict__ Wz,
    const float* __restrict__ Wh, const int* __restrict__ lev)
{
    extern __shared__ __align__(16) unsigned char sraw[];
    __nv_bfloat16 (*shAh)[KT + 8]  = (__nv_bfloat16(*)[KT + 8])(sraw + E_AH);
    __nv_bfloat16 (*shAl)[KT + 8]  = (__nv_bfloat16(*)[KT + 8])(sraw + E_AL);
    __nv_bfloat16 (*shBh)[HID + 8] = (__nv_bfloat16(*)[HID + 8])(sraw + E_BH);
    __nv_bfloat16 (*shBl)[HID + 8] = (__nv_bfloat16(*)[HID + 8])(sraw + E_BL);
    float (*shX)[68] = (float(*)[68])(sraw);
    float (*shW)[64] = (float(*)[64])(sraw + E_BH);

    int t = threadIdx.x;
    int rowbase = blockIdx.x * EROWS;

    int lane = t & 31;
    int wm = (t >> 5) & 3;
    int wn = (t >> 5) >> 2;
    uint32_t aAddrH = sptr(&shAh[wm * 16 + (lane & 15)][(lane >> 4) << 3]);
    uint32_t aAddrL = sptr(&shAl[wm * 16 + (lane & 15)][(lane >> 4) << 3]);
    uint32_t bAddrH = sptr(&shBh[lane & 15][wn * 32 + ((lane >> 4) << 3)]);
    uint32_t bAddrL = sptr(&shBl[lane & 15][wn * 32 + ((lane >> 4) << 3)]);

    float4 ar[4], er[4];
    load_A_dense64(ar, tfidf, rowbase, t, 0);
    load_E(er, Ew, t, 0);

    float acc[4][4] = {};

    for (int s = 0; s < STAGES_E; s++) {
        #pragma unroll
        for (int i = 0; i < 4; i++) {
            int u = t + i * 256, r = u >> 4, kq = u & 15;
            uint32_t h0, l0, h1, l1;
            split2(ar[i].x, ar[i].y, h0, l0);
            split2(ar[i].z, ar[i].w, h1, l1);
            *(uint2*)&shAh[r][kq * 4] = make_uint2(h0, h1);
            *(uint2*)&shAl[r][kq * 4] = make_uint2(l0, l1);
        }
        #pragma unroll
        for (int i = 0; i < 4; i++) {
            int u = t + i * 256, kr = u >> 4, kq = u & 15;
            uint32_t h0, l0, h1, l1;
            split2(er[i].x, er[i].y, h0, l0);
            split2(er[i].z, er[i].w, h1, l1);
            *(uint2*)&shBh[kr][kq * 4] = make_uint2(h0, h1);
            *(uint2*)&shBl[kr][kq * 4] = make_uint2(l0, l1);
        }
        __syncthreads();
        if (s + 1 < STAGES_E) {
            load_A_dense64(ar, tfidf, rowbase, t, (s + 1) * KT);
            load_E(er, Ew, t, (s + 1) * KT);
        }
        #pragma unroll
        for (int ks = 0; ks < KT / 16; ks++) {
            uint32_t a[4], al[4];
            ldsm_x4(a,  aAddrH + ks * 32);
            ldsm_x4(al, aAddrL + ks * 32);
            uint32_t bh[4], bl[4];
            ldsm_x4_t(bh, bAddrH + ks * 16 * B_ROW);
            ldsm_x4_t(bl, bAddrL + ks * 16 * B_ROW);
            MMA3(acc[0], a, al, bh[0], bh[1], bl[0], bl[1]);
            MMA3(acc[1], a, al, bh[2], bh[3], bl[2], bl[3]);
            ldsm_x4_t(bh, bAddrH + ks * 16 * B_ROW + 32);
            ldsm_x4_t(bl, bAddrL + ks * 16 * B_ROW + 32);
            MMA3(acc[2], a, al, bh[0], bh[1], bl[0], bl[1]);
            MMA3(acc[3], a, al, bh[2], bh[3], bl[2], bl[3]);
        }
        __syncthreads();
    }

    // x_hat fragments -> shX (fp32)
    int g = lane >> 2, tq = lane & 3;
    #pragma unroll
    for (int nb = 0; nb < 4; nb++) {
        int col = wn * 32 + nb * 8 + tq * 2;
        int rf = wm * 16 + g;
        shX[rf][col]         = acc[nb][0];
        shX[rf][col + 1]     = acc[nb][1];
        shX[rf + 8][col]     = acc[nb][2];
        shX[rf + 8][col + 1] = acc[nb][3];
    }

    const float* Ws[3] = {Wr, Wz, Wh};
    float*       Os[3] = {g_xr, g_xz, g_xh};
    int cq = t & 15, rq = t >> 4;
    int c0 = cq * 4, r0 = rq * 4;
    #pragma unroll
    for (int wI = 0; wI < 3; wI++) {
        __syncthreads();
        #pragma unroll
        for (int i = 0; i < 4; i++) {
            int u = t + i * 256;
            int kk = u >> 4, c4 = (u & 15) * 4;
            *(float4*)&shW[kk][c4] = *(const float4*)&Ws[wI][(size_t)kk * HID + c4];
        }
        __syncthreads();
        float o[4][4] = {};
        #pragma unroll 16
        for (int kk = 0; kk < HID; kk++) {
            float4 b = *(float4*)&shW[kk][c0];
            float a[4];
            #pragma unroll
            for (int i = 0; i < 4; i++) a[i] = shX[r0 + i][kk];
            #pragma unroll
            for (int i = 0; i < 4; i++) {
                o[i][0] += a[i] * b.x; o[i][1] += a[i] * b.y;
                o[i][2] += a[i] * b.z; o[i][3] += a[i] * b.w;
            }
        }
        #pragma unroll
        for (int i = 0; i < 4; i++)
            *(float4*)&Os[wI][(size_t)(rowbase + r0 + i) * HID + c0] =
                make_float4(o[i][0], o[i][1], o[i][2], o[i][3]);
    }

    // fused GRU for level-10 rows: hs == 0 -> h = sigmoid(xz) * tanh(xh)
    // each thread reads back exactly the addresses it just wrote (no sync needed)
    #pragma unroll
    for (int i = 0; i < 4; i++) {
        int row = rowbase + r0 + i;
        if (lev[row] == NLEV - 1) {
            size_t idx = (size_t)row * HID + c0;
            float4 xz = *(const float4*)&g_xz[idx];
            float4 xh = *(const float4*)&g_xh[idx];
            float hj[4];
            hj[0] = sigmoidf_(xz.x) * tanhf(xh.x);
            hj[1] = sigmoidf_(xz.y) * tanhf(xh.y);
            hj[2] = sigmoidf_(xz.z) * tanhf(xh.z);
            hj[3] = sigmoidf_(xz.w) * tanhf(xh.w);
            #pragma unroll
            for (int m = 0; m < 4; m++) {
                __nv_bfloat16 bh = __float2bfloat16(hj[m]);
                g_hbh[idx + m] = bh;
                g_hbl[idx + m] = __float2bfloat16(hj[m] - __bfloat162float(bh));
            }
        }
    }
}

// ---------------- final: gru(0) + root reduce + decode ----------------
__global__ __launch_bounds__(256) void final_kernel(
    const float* __restrict__ Ur, const float* __restrict__ Uz,
    const float* __restrict__ Uh, const float* __restrict__ dec_w,
    const float* __restrict__ dec_b, float* __restrict__ out)
{
    __shared__ __align__(16) unsigned char sraw[33536];
    __shared__ int lastf;
    __shared__ float red[4][HID];
    __shared__ float root[HID];

    int cnt = g_cnt[0], off = g_off[0];
    int ntile = (cnt + 31) >> 5;
    int t = threadIdx.x;

    for (int tile = blockIdx.x; tile < ntile; tile += FIN_BLKS)
        gru32(Ur, Uz, Uh, cnt, off, tile * 32, sraw, true);

    __threadfence();
    __syncthreads();
    if (t == 0) {
        int d = atomicAdd(&g_done[0], 1);
        lastf = (d == FIN_BLKS - 1);
    }
    __syncthreads();
    if (!lastf) return;
    __threadfence();

    int c = t & 63, q = t >> 6;
    float s = 0.f;
    for (int l = q; l < cnt; l += 4) {
        int gr = g_order[off + l];
        s += g_h[(size_t)gr * HID + c];
    }
    red[q][c] = s;
    __syncthreads();
    if (t < HID) root[t] = red[0][t] + red[1][t] + red[2][t] + red[3][t];
    __syncthreads();
    if (t < NCLS) {
        float a = dec_b[t];
        #pragma unroll 16
        for (int k = 0; k < HID; k++) a += root[k] * dec_w[k * NCLS + t];
        out[t] = a;
    }
}

// ---------------- launch ----------------
extern "C" void kernel_launch(void* const* d_in, const int* in_sizes, int n_in,
                              void* d_out, int out_size)
{
    const float* adj   = (const float*)d_in[0];
    const float* tfidf = (const float*)d_in[1];
    const int*   level = (const int*)d_in[2];
    const float* Ew    = (const float*)d_in[3];
    const float* Wr    = (const float*)d_in[4];
    const float* Wz    = (const float*)d_in[5];
    const float* Ur    = (const float*)d_in[6];
    const float* Uz    = (const float*)d_in[7];
    const float* Wh    = (const float*)d_in[8];
    const float* Uh    = (const float*)d_in[9];
    const float* dw    = (const float*)d_in[10];
    const float* db    = (const float*)d_in[11];
    float* out = (float*)d_out;

    cudaFuncSetAttribute(embed_kernel, cudaFuncAttributeMaxDynamicSharedMemorySize, SMEM_DYN);
    cudaFuncSetAttribute(aggru_kernel, cudaFuncAttributeMaxDynamicSharedMemorySize, SMEM_DYN);

    k_setup<<<2048, 256>>>();
    k_hist<<<64, 256>>>(level);
    k_scanscatter<<<1, 1024>>>(level);
    // index 3: embed (whole chip) + fused gru(10); agg(10) skipped (h == 0)
    embed_kernel<<<EMB_BLKS, THREADS, SMEM_DYN>>>(tfidf, Ew, Wr, Wz, Wh, level);
    for (int j = NLEV - 2; j >= 0; j--)
        aggru_kernel<<<AGG_BLKS, THREADS, SMEM_DYN>>>(adj, Ur, Uz, Uh, j, j < NLEV - 2);
    final_kernel<<<FIN_BLKS, 256>>>(Ur, Uz, Uh, dw, db, out);
}

// round 17
// speedup vs baseline: 2.0021x; 1.0083x over previous
#include <cuda_runtime.h>
#include <cuda_bf16.h>
#include <math.h>
#include <stdint.h>

#define N       16384
#define IN_DIM  5000
#define HID     64
#define NCLS    4
#define NLEV    11
#define KSPLIT  64
#define KCHUNK  (N / KSPLIT)               /* 256 */
#define KT      64
#define STAGES_A (KCHUNK / KT)             /* 4 */
#define STAGES_E ((IN_DIM + KT - 1) / KT)  /* 79 */
#define RROWS   128
#define THREADS 256
#define AGG_BLKS 296
#define EROWS   64
#define EMB_BLKS (N / EROWS)               /* 256 */

// agg smem layout
#define OFF_AH   0                          /* 128 x 72 bf16 = 18432 */
#define OFF_AL   18432
#define OFF_BH   36864                      /* 64 x 72 bf16 = 9216 */
#define OFF_BL   46080
#define OFF_ROWS 55296                      /* 128 ints */
#define SMEM_DYN 55824
// embed smem layout (64-row A tiles)
#define E_AH 0
#define E_AL 9216
#define E_BH 18432
#define E_BL 27648
// gru smem layout (reuses same dynamic smem between barriers)
#define G_U    0                            /* 64 x 65 f32 = 16640 */
#define G_HS   16640                        /* 32 x 65 f32 = 8320 */
#define G_RH   24960
#define G_ROWS 33280                        /* 32 ints */

#define A_ROW 144
#define B_ROW 144

// ---------------- device scratch ----------------
__device__ float g_h  [N * HID];
__device__ float g_hs [N * HID];
__device__ float g_xr [N * HID];
__device__ float g_xz [N * HID];
__device__ float g_xh [N * HID];
__device__ __nv_bfloat16 g_hbh[N * HID];
__device__ __nv_bfloat16 g_hbl[N * HID];
__device__ int   g_order[N];
__device__ int   g_cnt[NLEV];
__device__ int   g_cur[NLEV];
__device__ int   g_off[NLEV + 1];
__device__ int   g_phase[32];

__device__ __forceinline__ float sigmoidf_(float x) {
    return 1.0f / (1.0f + expf(-x));
}

// ---------------- asm helpers ----------------
__device__ __forceinline__ uint32_t sptr(const void* p) {
    return (uint32_t)__cvta_generic_to_shared(p);
}
__device__ __forceinline__ void ldsm_x4(uint32_t* r, uint32_t addr) {
    asm volatile("ldmatrix.sync.aligned.m8n8.x4.shared.b16 {%0,%1,%2,%3}, [%4];"
                 : "=r"(r[0]), "=r"(r[1]), "=r"(r[2]), "=r"(r[3]) : "r"(addr));
}
__device__ __forceinline__ void ldsm_x4_t(uint32_t* r, uint32_t addr) {
    asm volatile("ldmatrix.sync.aligned.m8n8.x4.trans.shared.b16 {%0,%1,%2,%3}, [%4];"
                 : "=r"(r[0]), "=r"(r[1]), "=r"(r[2]), "=r"(r[3]) : "r"(addr));
}
__device__ __forceinline__ void mma_bf16(float* c, const uint32_t* a,
                                         uint32_t b0, uint32_t b1) {
    asm volatile("mma.sync.aligned.m16n8k16.row.col.f32.bf16.bf16.f32 "
                 "{%0,%1,%2,%3}, {%4,%5,%6,%7}, {%8,%9}, {%0,%1,%2,%3};"
                 : "+f"(c[0]), "+f"(c[1]), "+f"(c[2]), "+f"(c[3])
                 : "r"(a[0]), "r"(a[1]), "r"(a[2]), "r"(a[3]), "r"(b0), "r"(b1));
}
__device__ __forceinline__ void split2(float x, float y, uint32_t& hi, uint32_t& lo) {
    __nv_bfloat162 h = __floats2bfloat162_rn(x, y);
    float rx = x - __bfloat162float(h.x);
    float ry = y - __bfloat162float(h.y);
    __nv_bfloat162 l = __floats2bfloat162_rn(rx, ry);
    union { __nv_bfloat162 h; uint32_t u; } ch, cl;
    ch.h = h; cl.h = l;
    hi = ch.u; lo = cl.u;
}

#define MMA3(ACC, AHI, ALO, BH0, BH1, BL0, BL1) \
    do { mma_bf16(ACC, AHI, BH0, BH1); mma_bf16(ACC, AHI, BL0, BL1); \
         mma_bf16(ACC, ALO, BH0, BH1); } while (0)

// grid barrier over AGG_BLKS resident blocks
__device__ __forceinline__ void gbar(int ph) {
    __syncthreads();
    if (threadIdx.x == 0) {
        __threadfence();
        atomicAdd(&g_phase[ph], 1);
        volatile int* vp = &g_phase[ph];
        while (*vp < AGG_BLKS) __nanosleep(64);
        __threadfence();
    }
    __syncthreads();
}

// ---------------- bookkeeping ----------------
__global__ void k_setup() {
    int idx = blockIdx.x * blockDim.x + threadIdx.x;
    if (blockIdx.x == 0 && threadIdx.x < 32) {
        if (threadIdx.x < NLEV) { g_cnt[threadIdx.x] = 0; g_cur[threadIdx.x] = 0; }
        g_phase[threadIdx.x] = 0;
    }
    const int NH4 = (N * HID) / 4;
    const int HB4 = (N * HID) / 8;
    float4 z = make_float4(0.f, 0.f, 0.f, 0.f);
    if (idx < NH4)                 ((float4*)g_hs )[idx]             = z;
    else if (idx < NH4 + HB4)      ((float4*)g_hbh)[idx - NH4]       = z;
    else if (idx < NH4 + 2 * HB4)  ((float4*)g_hbl)[idx - NH4 - HB4] = z;
}

__global__ void k_hist(const int* __restrict__ level) {
    int i = blockIdx.x * blockDim.x + threadIdx.x;
    if (i < N) atomicAdd(&g_cnt[level[i]], 1);
}

__global__ void k_scanscatter(const int* __restrict__ level) {
    int t = threadIdx.x;
    if (t == 0) {
        g_off[0] = 0;
        for (int l = 0; l < NLEV; l++) g_off[l + 1] = g_off[l] + g_cnt[l];
    }
    __syncthreads();
    for (int i = t; i < N; i += blockDim.x) {
        int lv = level[i];
        int p  = atomicAdd(&g_cur[lv], 1);
        g_order[g_off[lv] + p] = i;
    }
}

// ---------------- GRU for one 32-row tile (256 threads, smem scratch) ----------------
__device__ void gru32(const float* __restrict__ Ur, const float* __restrict__ Uz,
                      const float* __restrict__ Uh, int cnt, int off, int rb,
                      unsigned char* sraw, bool writeH)
{
    float (*shU )[HID + 1] = (float(*)[HID + 1])(sraw + G_U);
    float (*shHs)[HID + 1] = (float(*)[HID + 1])(sraw + G_HS);
    float (*shRh)[HID + 1] = (float(*)[HID + 1])(sraw + G_RH);
    int* shRows = (int*)(sraw + G_ROWS);
    int t = threadIdx.x;
    int c = t & 63, rg = t >> 6;

    __syncthreads();
    if (t < 32) shRows[t] = (rb + t < cnt) ? g_order[off + rb + t] : -1;
    __syncthreads();

    #pragma unroll
    for (int i = 0; i < 8; i++) {
        int u = t + i * 256, r = u >> 6, cc = u & 63;
        int gr = shRows[r];
        shHs[r][cc] = (gr >= 0) ? g_hs[(size_t)gr * HID + cc] : 0.0f;
    }
    #pragma unroll
    for (int i = 0; i < 16; i++) { int u = t + i * 256; shU[u >> 6][u & 63] = Ur[u]; }
    __syncthreads();

    float zv[8], hsv[8];

    #pragma unroll
    for (int i = 0; i < 8; i++) {
        int r = rg + 4 * i;
        int gr = shRows[r];
        float s = 0.f;
        #pragma unroll 16
        for (int kk = 0; kk < HID; kk++) s += shHs[r][kk] * shU[kk][c];
        float rj = (gr >= 0) ? sigmoidf_(g_xr[(size_t)gr * HID + c] + s) : 0.0f;
        shRh[r][c] = rj * shHs[r][c];
    }
    __syncthreads();
    #pragma unroll
    for (int i = 0; i < 16; i++) { int u = t + i * 256; shU[u >> 6][u & 63] = Uz[u]; }
    __syncthreads();

    #pragma unroll
    for (int i = 0; i < 8; i++) {
        int r = rg + 4 * i;
        int gr = shRows[r];
        float s = 0.f;
        #pragma unroll 16
        for (int kk = 0; kk < HID; kk++) s += shHs[r][kk] * shU[kk][c];
        zv[i]  = (gr >= 0) ? sigmoidf_(g_xz[(size_t)gr * HID + c] + s) : 0.0f;
        hsv[i] = shHs[r][c];
    }
    __syncthreads();
    #pragma unroll
    for (int i = 0; i < 16; i++) { int u = t + i * 256; shU[u >> 6][u & 63] = Uh[u]; }
    __syncthreads();

    #pragma unroll
    for (int i = 0; i < 8; i++) {
        int r = rg + 4 * i;
        int gr = shRows[r];
        if (gr < 0) continue;
        float s = 0.f;
        #pragma unroll 16
        for (int kk = 0; kk < HID; kk++) s += shRh[r][kk] * shU[kk][c];
        float hh = tanhf(g_xh[(size_t)gr * HID + c] + s);
        float hj = (1.0f - zv[i]) * hsv[i] + zv[i] * hh;
        size_t idx = (size_t)gr * HID + c;
        if (writeH) g_h[idx] = hj;
        __nv_bfloat16 bh = __float2bfloat16(hj);
        g_hbh[idx] = bh;
        g_hbl[idx] = __float2bfloat16(hj - __bfloat162float(bh));
    }
}

// ---------------- loaders ----------------
__device__ __forceinline__ void load_A_gather(float4* ar, const float* __restrict__ src,
                                              const int* shRows, int t, int k0) {
    #pragma unroll
    for (int i = 0; i < 8; i++) {
        int u = t + i * 256, r = u >> 4, kq = u & 15;
        int grow = shRows[r];
        float4 v = make_float4(0.f, 0.f, 0.f, 0.f);
        if (grow >= 0) v = *(const float4*)(src + (size_t)grow * N + k0 + kq * 4);
        ar[i] = v;
    }
}
__device__ __forceinline__ void load_A_dense64(float4* ar, const float* __restrict__ src,
                                               int rowbase, int t, int k0) {
    #pragma unroll
    for (int i = 0; i < 4; i++) {
        int u = t + i * 256, r = u >> 4, kq = u & 15;
        int k = k0 + kq * 4;
        float4 v = make_float4(0.f, 0.f, 0.f, 0.f);
        const float* p = src + (size_t)(rowbase + r) * IN_DIM + k;
        if (k + 3 < IN_DIM) v = *(const float4*)p;
        else if (k < IN_DIM) {
            float tmp[4] = {0.f, 0.f, 0.f, 0.f};
            #pragma unroll
            for (int m = 0; m < 4; m++) if (k + m < IN_DIM) tmp[m] = p[m];
            v = make_float4(tmp[0], tmp[1], tmp[2], tmp[3]);
        }
        ar[i] = v;
    }
}
__device__ __forceinline__ void load_H(uint4* hh, uint4* hl, int t, int k0) {
    #pragma unroll
    for (int i = 0; i < 2; i++) {
        int u = t + i * 256, kr = u >> 3, q = u & 7;
        size_t idx = (size_t)(k0 + kr) * HID + q * 8;
        hh[i] = *(const uint4*)&g_hbh[idx];
        hl[i] = *(const uint4*)&g_hbl[idx];
    }
}
__device__ __forceinline__ void load_E(float4* er, const float* __restrict__ Ew,
                                       int t, int k0) {
    #pragma unroll
    for (int i = 0; i < 4; i++) {
        int u = t + i * 256, kr = u >> 4, kq = u & 15;
        int k = k0 + kr;
        float4 v = make_float4(0.f, 0.f, 0.f, 0.f);
        if (k < IN_DIM) v = *(const float4*)&Ew[(size_t)k * HID + kq * 4];
        er[i] = v;
    }
}

// ---------------- agg (128x64 block tile, persistent), first tile may be prefetched ----
__device__ void agg_body(const float* __restrict__ adj, int j,
                         unsigned char* sraw, int bid, int nblk,
                         float4* arPre, bool havePre)
{
    int* shRows = (int*)(sraw + OFF_ROWS);

    int cnt = g_cnt[j];
    int off = g_off[j];
    int nRow = (cnt + RROWS - 1) / RROWS;
    int ntile = nRow * KSPLIT;
    int t = threadIdx.x;

    int lane = t & 31;
    int w  = t >> 5;
    int wm = w & 3;
    int wn = w >> 2;
    uint32_t smemBase = sptr(sraw);
    uint32_t aRel = (uint32_t)((wm * 32 + (lane & 15)) * A_ROW + (((lane >> 4) << 3) << 1));
    uint32_t bRel = (uint32_t)((lane & 15) * B_ROW + ((wn * 32 + ((lane >> 4) << 3)) << 1));
    int g = lane >> 2, tq = lane & 3;

    for (int tile = bid; tile < ntile; tile += nblk) {
        int rbi = tile % nRow;
        int ks  = tile / nRow;
        int rb  = rbi * RROWS;
        int kbase = ks * KCHUNK;

        __syncthreads();
        if (t < RROWS) shRows[t] = (rb + t < cnt) ? g_order[off + rb + t] : -1;
        __syncthreads();

        float4 ar[8];
        uint4  hh[2], hl[2];
        if (tile == bid && havePre) {
            #pragma unroll
            for (int i = 0; i < 8; i++) ar[i] = arPre[i];
        } else {
            load_A_gather(ar, adj, shRows, t, kbase);
        }
        load_H(hh, hl, t, kbase);

        float acc[2][4][4] = {};

        for (int s = 0; s < STAGES_A; s++) {
            {
                __nv_bfloat16 (*shAh)[KT + 8] = (__nv_bfloat16(*)[KT + 8])(sraw + OFF_AH);
                __nv_bfloat16 (*shAl)[KT + 8] = (__nv_bfloat16(*)[KT + 8])(sraw + OFF_AL);
                #pragma unroll
                for (int i = 0; i < 8; i++) {
                    int u = t + i * 256, r = u >> 4, kq = u & 15;
                    uint32_t h0, l0, h1, l1;
                    split2(ar[i].x, ar[i].y, h0, l0);
                    split2(ar[i].z, ar[i].w, h1, l1);
                    *(uint2*)&shAh[r][kq * 4] = make_uint2(h0, h1);
                    *(uint2*)&shAl[r][kq * 4] = make_uint2(l0, l1);
                }
                __nv_bfloat16 (*shBh)[HID + 8] = (__nv_bfloat16(*)[HID + 8])(sraw + OFF_BH);
                __nv_bfloat16 (*shBl)[HID + 8] = (__nv_bfloat16(*)[HID + 8])(sraw + OFF_BL);
                #pragma unroll
                for (int i = 0; i < 2; i++) {
                    int u = t + i * 256, kr = u >> 3, q = u & 7;
                    *(uint4*)&shBh[kr][q * 8] = hh[i];
                    *(uint4*)&shBl[kr][q * 8] = hl[i];
                }
            }
            __syncthreads();
            if (s + 1 < STAGES_A) {
                int k0 = kbase + (s + 1) * KT;
                load_A_gather(ar, adj, shRows, t, k0);
                load_H(hh, hl, t, k0);
            }
            uint32_t aAddrH = smemBase + OFF_AH + aRel;
            uint32_t aAddrL = smemBase + OFF_AL + aRel;
            uint32_t bAddrH = smemBase + OFF_BH + bRel;
            uint32_t bAddrL = smemBase + OFF_BL + bRel;
            #pragma unroll
            for (int kss = 0; kss < KT / 16; kss++) {
                uint32_t ah[2][4], al[2][4];
                ldsm_x4(ah[0], aAddrH + kss * 32);
                ldsm_x4(ah[1], aAddrH + 16 * A_ROW + kss * 32);
                ldsm_x4(al[0], aAddrL + kss * 32);
                ldsm_x4(al[1], aAddrL + 16 * A_ROW + kss * 32);
                uint32_t bh0[4], bl0[4], bh1[4], bl1[4];
                ldsm_x4_t(bh0, bAddrH + kss * 16 * B_ROW);
                ldsm_x4_t(bl0, bAddrL + kss * 16 * B_ROW);
                ldsm_x4_t(bh1, bAddrH + kss * 16 * B_ROW + 32);
                ldsm_x4_t(bl1, bAddrL + kss * 16 * B_ROW + 32);
                #pragma unroll
                for (int mt = 0; mt < 2; mt++) {
                    MMA3(acc[mt][0], ah[mt], al[mt], bh0[0], bh0[1], bl0[0], bl0[1]);
                    MMA3(acc[mt][1], ah[mt], al[mt], bh0[2], bh0[3], bl0[2], bl0[3]);
                    MMA3(acc[mt][2], ah[mt], al[mt], bh1[0], bh1[1], bl1[0], bl1[1]);
                    MMA3(acc[mt][3], ah[mt], al[mt], bh1[2], bh1[3], bl1[2], bl1[3]);
                }
            }
            __syncthreads();
        }

        #pragma unroll
        for (int mt = 0; mt < 2; mt++) {
            #pragma unroll
            for (int nb = 0; nb < 4; nb++) {
                int col = wn * 32 + nb * 8 + tq * 2;
                int r0 = wm * 32 + mt * 16 + g;
                int gr0 = shRows[r0];
                if (gr0 >= 0) {
                    atomicAdd(&g_hs[(size_t)gr0 * HID + col],     acc[mt][nb][0]);
                    atomicAdd(&g_hs[(size_t)gr0 * HID + col + 1], acc[mt][nb][1]);
                }
                int gr1 = shRows[r0 + 8];
                if (gr1 >= 0) {
                    atomicAdd(&g_hs[(size_t)gr1 * HID + col],     acc[mt][nb][2]);
                    atomicAdd(&g_hs[(size_t)gr1 * HID + col + 1], acc[mt][nb][3]);
                }
            }
        }
    }
}

// ---------------- master: all levels + final, one persistent launch ----------------
__global__ __launch_bounds__(THREADS, 2) void master_kernel(
    const float* __restrict__ adj, const float* __restrict__ Ur,
    const float* __restrict__ Uz, const float* __restrict__ Uh,
    const float* __restrict__ dec_w, const float* __restrict__ dec_b,
    float* __restrict__ out)
{
    extern __shared__ __align__(16) unsigned char sraw[];
    int bid = blockIdx.x;
    int t = threadIdx.x;
    int ph = 0;

    for (int j = NLEV - 2; j >= 0; j--) {
        bool didGru = false;
        if (j < NLEV - 2) {
            int cntP = g_cnt[j + 1], offP = g_off[j + 1];
            int ntG = (cntP + 31) >> 5;
            if (bid < ntG) {
                for (int tile = bid; tile < ntG; tile += AGG_BLKS)
                    gru32(Ur, Uz, Uh, cntP, offP, tile * 32, sraw, false);
                didGru = true;
            }
        }
        // prefetch first agg tile A (depends only on adj/g_order — safe pre-barrier)
        int cnt = g_cnt[j], off = g_off[j];
        int nRow = (cnt + RROWS - 1) / RROWS;
        int ntile = nRow * KSPLIT;
        float4 arPre[8];
        bool havePre = false;
        if (!didGru && bid < ntile) {
            int rbi = bid % nRow, ks = bid / nRow;
            int rb = rbi * RROWS, kbase = ks * KCHUNK;
            #pragma unroll
            for (int i = 0; i < 8; i++) {
                int u = t + i * 256, r = u >> 4, kq = u & 15;
                int grow = (rb + r < cnt) ? g_order[off + rb + r] : -1;
                float4 v = make_float4(0.f, 0.f, 0.f, 0.f);
                if (grow >= 0) v = *(const float4*)(adj + (size_t)grow * N + kbase + kq * 4);
                arPre[i] = v;
            }
            havePre = true;
        }
        if (j < NLEV - 2) gbar(ph++);      // gru(j+1) done -> h ready
        agg_body(adj, j, sraw, bid, AGG_BLKS, arPre, havePre);
        gbar(ph++);                        // agg(j) atomics done -> hs ready
    }

    // gru(0): writes g_h for root rows
    {
        int cnt0 = g_cnt[0], off0 = g_off[0];
        int ntG = (cnt0 + 31) >> 5;
        for (int tile = bid; tile < ntG; tile += AGG_BLKS)
            gru32(Ur, Uz, Uh, cnt0, off0, tile * 32, sraw, true);
    }
    gbar(ph++);

    if (bid != 0) return;

    // root reduce + decode (block 0)
    __shared__ float red[4][HID];
    __shared__ float root[HID];
    int cnt = g_cnt[0], off = g_off[0];
    int c = t & 63, q = t >> 6;
    float s = 0.f;
    for (int l = q; l < cnt; l += 4) {
        int gr = g_order[off + l];
        s += g_h[(size_t)gr * HID + c];
    }
    red[q][c] = s;
    __syncthreads();
    if (t < HID) root[t] = red[0][t] + red[1][t] + red[2][t] + red[3][t];
    __syncthreads();
    if (t < NCLS) {
        float a = dec_b[t];
        #pragma unroll 16
        for (int k = 0; k < HID; k++) a += root[k] * dec_w[k * NCLS + t];
        out[t] = a;
    }
}

// ---------------- embed (64-row tiles) + fused gru(level 10) ----------------
__global__ __launch_bounds__(THREADS, 2) void embed_kernel(
    const float* __restrict__ tfidf, const float* __restrict__ Ew,
    const float* __restrict__ Wr, const float* __restrict__ Wz,
    const float* __restrict__ Wh, const int* __restrict__ lev)
{
    extern __shared__ __align__(16) unsigned char sraw[];
    __nv_bfloat16 (*shAh)[KT + 8]  = (__nv_bfloat16(*)[KT + 8])(sraw + E_AH);
    __nv_bfloat16 (*shAl)[KT + 8]  = (__nv_bfloat16(*)[KT + 8])(sraw + E_AL);
    __nv_bfloat16 (*shBh)[HID + 8] = (__nv_bfloat16(*)[HID + 8])(sraw + E_BH);
    __nv_bfloat16 (*shBl)[HID + 8] = (__nv_bfloat16(*)[HID + 8])(sraw + E_BL);
    float (*shX)[68] = (float(*)[68])(sraw);
    float (*shW)[64] = (float(*)[64])(sraw + E_BH);

    int t = threadIdx.x;
    int rowbase = blockIdx.x * EROWS;

    int lane = t & 31;
    int wm = (t >> 5) & 3;
    int wn = (t >> 5) >> 2;
    uint32_t aAddrH = sptr(&shAh[wm * 16 + (lane & 15)][(lane >> 4) << 3]);
    uint32_t aAddrL = sptr(&shAl[wm * 16 + (lane & 15)][(lane >> 4) << 3]);
    uint32_t bAddrH = sptr(&shBh[lane & 15][wn * 32 + ((lane >> 4) << 3)]);
    uint32_t bAddrL = sptr(&shBl[lane & 15][wn * 32 + ((lane >> 4) << 3)]);

    float4 ar[4], er[4];
    load_A_dense64(ar, tfidf, rowbase, t, 0);
    load_E(er, Ew, t, 0);

    float acc[4][4] = {};

    for (int s = 0; s < STAGES_E; s++) {
        #pragma unroll
        for (int i = 0; i < 4; i++) {
            int u = t + i * 256, r = u >> 4, kq = u & 15;
            uint32_t h0, l0, h1, l1;
            split2(ar[i].x, ar[i].y, h0, l0);
            split2(ar[i].z, ar[i].w, h1, l1);
            *(uint2*)&shAh[r][kq * 4] = make_uint2(h0, h1);
            *(uint2*)&shAl[r][kq * 4] = make_uint2(l0, l1);
        }
        #pragma unroll
        for (int i = 0; i < 4; i++) {
            int u = t + i * 256, kr = u >> 4, kq = u & 15;
            uint32_t h0, l0, h1, l1;
            split2(er[i].x, er[i].y, h0, l0);
            split2(er[i].z, er[i].w, h1, l1);
            *(uint2*)&shBh[kr][kq * 4] = make_uint2(h0, h1);
            *(uint2*)&shBl[kr][kq * 4] = make_uint2(l0, l1);
        }
        __syncthreads();
        if (s + 1 < STAGES_E) {
            load_A_dense64(ar, tfidf, rowbase, t, (s + 1) * KT);
            load_E(er, Ew, t, (s + 1) * KT);
        }
        #pragma unroll
        for (int ks = 0; ks < KT / 16; ks++) {
            uint32_t a[4], al[4];
            ldsm_x4(a,  aAddrH + ks * 32);
            ldsm_x4(al, aAddrL + ks * 32);
            uint32_t bh[4], bl[4];
            ldsm_x4_t(bh, bAddrH + ks * 16 * B_ROW);
            ldsm_x4_t(bl, bAddrL + ks * 16 * B_ROW);
            MMA3(acc[0], a, al, bh[0], bh[1], bl[0], bl[1]);
            MMA3(acc[1], a, al, bh[2], bh[3], bl[2], bl[3]);
            ldsm_x4_t(bh, bAddrH + ks * 16 * B_ROW + 32);
            ldsm_x4_t(bl, bAddrL + ks * 16 * B_ROW + 32);
            MMA3(acc[2], a, al, bh[0], bh[1], bl[0], bl[1]);
            MMA3(acc[3], a, al, bh[2], bh[3], bl[2], bl[3]);
        }
        __syncthreads();
    }

    int g = lane >> 2, tq = lane & 3;
    #pragma unroll
    for (int nb = 0; nb < 4; nb++) {
        int col = wn * 32 + nb * 8 + tq * 2;
        int rf = wm * 16 + g;
        shX[rf][col]         = acc[nb][0];
        shX[rf][col + 1]     = acc[nb][1];
        shX[rf + 8][col]     = acc[nb][2];
        shX[rf + 8][col + 1] = acc[nb][3];
    }

    const float* Ws[3] = {Wr, Wz, Wh};
    float*       Os[3] = {g_xr, g_xz, g_xh};
    int cq = t & 15, rq = t >> 4;
    int c0 = cq * 4, r0 = rq * 4;
    #pragma unroll
    for (int wI = 0; wI < 3; wI++) {
        __syncthreads();
        #pragma unroll
        for (int i = 0; i < 4; i++) {
            int u = t + i * 256;
            int kk = u >> 4, c4 = (u & 15) * 4;
            *(float4*)&shW[kk][c4] = *(const float4*)&Ws[wI][(size_t)kk * HID + c4];
        }
        __syncthreads();
        float o[4][4] = {};
        #pragma unroll 16
        for (int kk = 0; kk < HID; kk++) {
            float4 b = *(float4*)&shW[kk][c0];
            float a[4];
            #pragma unroll
            for (int i = 0; i < 4; i++) a[i] = shX[r0 + i][kk];
            #pragma unroll
            for (int i = 0; i < 4; i++) {
                o[i][0] += a[i] * b.x; o[i][1] += a[i] * b.y;
                o[i][2] += a[i] * b.z; o[i][3] += a[i] * b.w;
            }
        }
        #pragma unroll
        for (int i = 0; i < 4; i++)
            *(float4*)&Os[wI][(size_t)(rowbase + r0 + i) * HID + c0] =
                make_float4(o[i][0], o[i][1], o[i][2], o[i][3]);
    }

    // fused GRU for level-10 rows: hs == 0 -> h = sigmoid(xz) * tanh(xh)
    #pragma unroll
    for (int i = 0; i < 4; i++) {
        int row = rowbase + r0 + i;
        if (lev[row] == NLEV - 1) {
            size_t idx = (size_t)row * HID + c0;
            float4 xz = *(const float4*)&g_xz[idx];
            float4 xh = *(const float4*)&g_xh[idx];
            float hj[4];
            hj[0] = sigmoidf_(xz.x) * tanhf(xh.x);
            hj[1] = sigmoidf_(xz.y) * tanhf(xh.y);
            hj[2] = sigmoidf_(xz.z) * tanhf(xh.z);
            hj[3] = sigmoidf_(xz.w) * tanhf(xh.w);
            #pragma unroll
            for (int m = 0; m < 4; m++) {
                __nv_bfloat16 bh = __float2bfloat16(hj[m]);
                g_hbh[idx + m] = bh;
                g_hbl[idx + m] = __float2bfloat16(hj[m] - __bfloat162float(bh));
            }
        }
    }
}

// ---------------- launch ----------------
extern "C" void kernel_launch(void* const* d_in, const int* in_sizes, int n_in,
                              void* d_out, int out_size)
{
    const float* adj   = (const float*)d_in[0];
    const float* tfidf = (const float*)d_in[1];
    const int*   level = (const int*)d_in[2];
    const float* Ew    = (const float*)d_in[3];
    const float* Wr    = (const float*)d_in[4];
    const float* Wz    = (const float*)d_in[5];
    const float* Ur    = (const float*)d_in[6];
    const float* Uz    = (const float*)d_in[7];
    const float* Wh    = (const float*)d_in[8];
    const float* Uh    = (const float*)d_in[9];
    const float* dw    = (const float*)d_in[10];
    const float* db    = (const float*)d_in[11];
    float* out = (float*)d_out;

    cudaFuncSetAttribute(embed_kernel,  cudaFuncAttributeMaxDynamicSharedMemorySize, SMEM_DYN);
    cudaFuncSetAttribute(master_kernel, cudaFuncAttributeMaxDynamicSharedMemorySize, SMEM_DYN);

    k_setup<<<2048, 256>>>();
    k_hist<<<64, 256>>>(level);
    k_scanscatter<<<1, 1024>>>(level);
    embed_kernel<<<EMB_BLKS, THREADS, SMEM_DYN>>>(tfidf, Ew, Wr, Wz, Wh, level);
    master_kernel<<<AGG_BLKS, THREADS, SMEM_DYN>>>(adj, Ur, Uz, Uh, dw, db, out);
}